// round 14
// baseline (speedup 1.0000x reference)
#include <cuda_runtime.h>
#include <cuda_fp16.h>
#include <cstddef>
#include <cstdint>

#define HW    4096
#define NK    256
#define DIM   512
#define NSPL  4   // key splits for attention

// ---------------- scratch (no allocation allowed) ----------------
__device__ float  g_auxp[2048u  * 512u];         // tf32-prepped aux
__device__ float  g_wq  [512u * 512u];
__device__ float  g_wo  [512u * 512u];
__device__ float  g_wkv [512u * 1024u];          // interleaved prepped Wk|Wv
__device__ float  g_bkv [1024u];
__device__ __half g_q [2048u  * 512u];           // half, 0.125 scale folded
__device__ __half g_k [32768u * 512u];           // half K
__device__ __half g_v [32768u * 512u];           // half V
__device__ float  g_ao [2048u * 512u];
__device__ float  g_aop[4u * 2048u * 512u];      // partial O per key-quarter
__device__ float  g_x [2048u  * 512u];
__device__ float  g_ml[64u * 4u * 4u * 64u * 2u];
__device__ float  g_attn_fb[(size_t)64 * 256 * 4096];

// ---------------- helpers ----------------
__device__ __forceinline__ unsigned f2tf(float x) {
    unsigned r;
    asm("cvt.rna.tf32.f32 %0, %1;" : "=r"(r) : "f"(x));
    return r;
}
__device__ __forceinline__ float rtf(float x) { return __uint_as_float(f2tf(x)); }
__device__ __forceinline__ unsigned f2h2(float a, float b) {
    __half2 h = __floats2half2_rn(a, b);
    return *(unsigned*)&h;
}
__device__ __forceinline__ void mma_tf32(float* c, const unsigned* a, const unsigned* b) {
    asm volatile(
        "mma.sync.aligned.m16n8k8.row.col.f32.tf32.tf32.f32 "
        "{%0,%1,%2,%3}, {%4,%5,%6,%7}, {%8,%9}, {%0,%1,%2,%3};\n"
        : "+f"(c[0]), "+f"(c[1]), "+f"(c[2]), "+f"(c[3])
        : "r"(a[0]), "r"(a[1]), "r"(a[2]), "r"(a[3]), "r"(b[0]), "r"(b[1]));
}
__device__ __forceinline__ void mma_f16(float* c, const unsigned* a, const unsigned* b) {
    asm volatile(
        "mma.sync.aligned.m16n8k16.row.col.f32.f16.f16.f32 "
        "{%0,%1,%2,%3}, {%4,%5,%6,%7}, {%8,%9}, {%0,%1,%2,%3};\n"
        : "+f"(c[0]), "+f"(c[1]), "+f"(c[2]), "+f"(c[3])
        : "r"(a[0]), "r"(a[1]), "r"(a[2]), "r"(a[3]), "r"(b[0]), "r"(b[1]));
}
__device__ __forceinline__ void ldsm4(unsigned& r0, unsigned& r1, unsigned& r2,
                                      unsigned& r3, uint32_t addr) {
    asm volatile("ldmatrix.sync.aligned.m8n8.x4.shared.b16 {%0,%1,%2,%3}, [%4];"
                 : "=r"(r0), "=r"(r1), "=r"(r2), "=r"(r3) : "r"(addr));
}
__device__ __forceinline__ void ldsm4t(unsigned& r0, unsigned& r1, unsigned& r2,
                                       unsigned& r3, uint32_t addr) {
    asm volatile("ldmatrix.sync.aligned.m8n8.x4.trans.shared.b16 {%0,%1,%2,%3}, [%4];"
                 : "=r"(r0), "=r"(r1), "=r"(r2), "=r"(r3) : "r"(addr));
}
__device__ __forceinline__ void cp16(void* dst, const void* src) {
    unsigned d = (unsigned)__cvta_generic_to_shared(dst);
    asm volatile("cp.async.cg.shared.global [%0], [%1], 16;" :: "r"(d), "l"(src));
}
__device__ __forceinline__ void cpcommit() { asm volatile("cp.async.commit_group;"); }
template<int N> __device__ __forceinline__ void cpwait() {
    asm volatile("cp.async.wait_group %0;" :: "n"(N));
}

// =================================================================
// Prep: tf32-round aux, Wq, Wo; build interleaved Wkv [512][1024] + bkv.
// segments (float4): aux 262144 | wq 65536 | wo 65536 | wkv 131072 | bkv 256
// =================================================================
__global__ void prep_small(const float4* __restrict__ aux,
                           const float4* __restrict__ wq, const float4* __restrict__ wo,
                           const float4* __restrict__ wk, const float4* __restrict__ wv,
                           const float4* __restrict__ bk, const float4* __restrict__ bv,
                           float4* __restrict__ auxp,
                           float4* __restrict__ pwq, float4* __restrict__ pwo,
                           float4* __restrict__ pwkv, float4* __restrict__ pbkv) {
    size_t i = (size_t)blockIdx.x * 512 + threadIdx.x;
    if (i >= 524544) return;
    const float4* s; float4* d;
    if (i < 262144)      { s = aux + i;           d = auxp + i; }
    else if (i < 327680) { s = wq + (i - 262144); d = pwq + (i - 262144); }
    else if (i < 393216) { s = wo + (i - 327680); d = pwo + (i - 327680); }
    else if (i < 524288) {
        size_t j = i - 393216;
        size_t row = j >> 8, c4 = j & 255;
        s = (c4 < 128) ? (wk + row * 128 + c4) : (wv + row * 128 + (c4 - 128));
        d = pwkv + j;
    } else {
        size_t j = i - 524288;
        s = (j < 128) ? (bk + j) : (bv + (j - 128));
        d = pbkv + j;
    }
    float4 v = *s;
    *d = make_float4(rtf(v.x), rtf(v.y), rtf(v.z), rtf(v.w));
}

// =================================================================
// K or V half projection (tf32 mma): 128x64 CTA tile, BK=32,
// 4 warps (2m x 2n), warp tile 64x32, occ 3 (acc 64 regs). Output half.
// grid (8, 256), jbase selects K/V half.
// =================================================================
__global__ __launch_bounds__(128, 3)
void gemm_kv(const float* __restrict__ A, const float* __restrict__ W,
             const float* __restrict__ bias,
             __half* __restrict__ gk, __half* __restrict__ gv, int jbase)
{
    extern __shared__ float sm[];
    float* Abase = sm;                       // [2][32][136]
    float* Bbase = sm + 2 * 32 * 136;        // [2][32][72]

    const int tid = threadIdx.x;
    const int m0 = blockIdx.y * 128, j0 = jbase + blockIdx.x * 64;
    const int w = tid >> 5, lane = tid & 31, g = lane >> 2, tig = lane & 3;
    const int mw = (w >> 1) * 64, nw = (w & 1) * 32;

    auto loadA = [&](int buf, int c0) {
        float* dst = Abase + buf * 32 * 136;
        const int bb = m0 >> 12, n0 = m0 & 4095;
        #pragma unroll
        for (int i = 0; i < 8; i++) {
            int id = tid + i * 128;
            int k = id >> 5, m4 = (id & 31) * 4;
            cp16(dst + k * 136 + m4, A + ((size_t)(bb * 512 + c0 + k)) * 4096 + n0 + m4);
        }
    };
    auto loadB = [&](int buf, int c0) {
        float* dst = Bbase + buf * 32 * 72;
        #pragma unroll
        for (int i = 0; i < 4; i++) {
            int id = tid + i * 128;
            int k = id >> 4, n4 = (id & 15) * 4;
            cp16(dst + k * 72 + n4, W + (size_t)(c0 + k) * 1024 + j0 + n4);
        }
    };

    float acc[4][4][4];
    #pragma unroll
    for (int i = 0; i < 4; i++)
        #pragma unroll
        for (int j = 0; j < 4; j++)
            #pragma unroll
            for (int r = 0; r < 4; r++) acc[i][j][r] = 0.f;

    loadA(0, 0); loadB(0, 0); cpcommit();
    for (int t = 0; t < 16; t++) {
        const int buf = t & 1;
        if (t < 15) { loadA(buf ^ 1, (t + 1) * 32); loadB(buf ^ 1, (t + 1) * 32); cpcommit(); cpwait<1>(); }
        else cpwait<0>();
        __syncthreads();
        const float* As = Abase + buf * 32 * 136;
        const float* Bs = Bbase + buf * 32 * 72;
        #pragma unroll
        for (int k8 = 0; k8 < 4; k8++) {
            const int kb = k8 * 8 + tig;
            unsigned af[4][4], bf[4][2];
            #pragma unroll
            for (int im = 0; im < 4; im++) {
                const int r = mw + im * 16 + g;
                af[im][0] = f2tf(As[kb * 136 + r]);
                af[im][1] = f2tf(As[kb * 136 + r + 8]);
                af[im][2] = f2tf(As[(kb + 4) * 136 + r]);
                af[im][3] = f2tf(As[(kb + 4) * 136 + r + 8]);
            }
            #pragma unroll
            for (int jn = 0; jn < 4; jn++) {
                const int n = nw + jn * 8 + g;
                bf[jn][0] = __float_as_uint(Bs[kb * 72 + n]);
                bf[jn][1] = __float_as_uint(Bs[(kb + 4) * 72 + n]);
            }
            #pragma unroll
            for (int im = 0; im < 4; im++)
                #pragma unroll
                for (int jn = 0; jn < 4; jn++)
                    mma_tf32(acc[im][jn], af[im], bf[jn]);
        }
        __syncthreads();
    }
    __half* Cout = (j0 < 512) ? gk : gv;
    const int jb = j0 & 511;
    #pragma unroll
    for (int im = 0; im < 4; im++) {
        #pragma unroll
        for (int jn = 0; jn < 4; jn++) {
            const int r0 = m0 + mw + im * 16 + g;
            const int col = nw + jn * 8 + 2 * tig;
            const float* cc = acc[im][jn];
            #pragma unroll
            for (int half = 0; half < 2; half++) {
                const int r = r0 + half * 8;
                float v0 = cc[half * 2]     + bias[j0 + col];
                float v1 = cc[half * 2 + 1] + bias[j0 + col + 1];
                *(unsigned*)(Cout + (size_t)r * 512 + jb + col) = f2h2(v0, v1);
            }
        }
    }
}

// =================================================================
// Small projection GEMM (tf32). MODE 0: fp32 out (+resid);
// MODE 2: half out with 0.125 scale (Q projection).
// =================================================================
template<int MODE>
__global__ __launch_bounds__(128, 2)
void gemm128ca(const float* __restrict__ A, const float* __restrict__ W,
               const float* __restrict__ bias, const float* __restrict__ resid,
               float* __restrict__ C)
{
    extern __shared__ float sm[];
    float* Abase = sm;                   // [2][128][36]
    float* Bbase = sm + 2 * 128 * 36;    // [2][32][136]

    const int tid = threadIdx.x;
    const int m0 = blockIdx.y * 128, j0 = blockIdx.x * 128;
    const int w = tid >> 5, lane = tid & 31, g = lane >> 2, tig = lane & 3;
    const int mw = (w >> 1) * 64, nw = (w & 1) * 64;

    auto loadA = [&](int buf, int c0) {
        float* dst = Abase + buf * 128 * 36;
        #pragma unroll
        for (int i = 0; i < 8; i++) {
            int id = tid + i * 128;
            int m = id >> 3, c4 = (id & 7) * 4;
            cp16(dst + m * 36 + c4, A + (size_t)(m0 + m) * 512 + c0 + c4);
        }
    };
    auto loadB = [&](int buf, int c0) {
        float* dst = Bbase + buf * 32 * 136;
        #pragma unroll
        for (int i = 0; i < 8; i++) {
            int id = tid + i * 128;
            int k = id >> 5, n4 = (id & 31) * 4;
            cp16(dst + k * 136 + n4, W + (size_t)(c0 + k) * 512 + j0 + n4);
        }
    };

    float acc[4][8][4];
    #pragma unroll
    for (int i = 0; i < 4; i++)
        #pragma unroll
        for (int j = 0; j < 8; j++)
            #pragma unroll
            for (int r = 0; r < 4; r++) acc[i][j][r] = 0.f;

    loadA(0, 0); loadB(0, 0); cpcommit();
    for (int t = 0; t < 16; t++) {
        const int buf = t & 1;
        if (t < 15) { loadA(buf ^ 1, (t + 1) * 32); loadB(buf ^ 1, (t + 1) * 32); cpcommit(); cpwait<1>(); }
        else cpwait<0>();
        __syncthreads();
        const float* As = Abase + buf * 128 * 36;
        const float* Bs = Bbase + buf * 32 * 136;
        #pragma unroll
        for (int k8 = 0; k8 < 4; k8++) {
            const int kb = k8 * 8 + tig;
            unsigned af[4][4], bf[8][2];
            #pragma unroll
            for (int im = 0; im < 4; im++) {
                const int r = mw + im * 16 + g;
                af[im][0] = __float_as_uint(As[r * 36 + kb]);
                af[im][1] = __float_as_uint(As[(r + 8) * 36 + kb]);
                af[im][2] = __float_as_uint(As[r * 36 + kb + 4]);
                af[im][3] = __float_as_uint(As[(r + 8) * 36 + kb + 4]);
            }
            #pragma unroll
            for (int jn = 0; jn < 8; jn++) {
                const int n = nw + jn * 8 + g;
                bf[jn][0] = __float_as_uint(Bs[kb * 136 + n]);
                bf[jn][1] = __float_as_uint(Bs[(kb + 4) * 136 + n]);
            }
            #pragma unroll
            for (int im = 0; im < 4; im++)
                #pragma unroll
                for (int jn = 0; jn < 8; jn++)
                    mma_tf32(acc[im][jn], af[im], bf[jn]);
        }
        __syncthreads();
    }
    #pragma unroll
    for (int im = 0; im < 4; im++) {
        #pragma unroll
        for (int jn = 0; jn < 8; jn++) {
            const int r0 = m0 + mw + im * 16 + g;
            const int col = j0 + nw + jn * 8 + 2 * tig;
            const float* cc = acc[im][jn];
            #pragma unroll
            for (int half = 0; half < 2; half++) {
                const int r = r0 + half * 8;
                float v0 = cc[half * 2]     + bias[col];
                float v1 = cc[half * 2 + 1] + bias[col + 1];
                if (MODE == 0) {
                    if (resid) {
                        v0 += resid[(size_t)r * 512 + col];
                        v1 += resid[(size_t)r * 512 + col + 1];
                    }
                    *(float2*)(C + (size_t)r * 512 + col) = make_float2(v0, v1);
                } else {
                    __half* Ch = (__half*)C;
                    *(unsigned*)(Ch + (size_t)r * 512 + col) = f2h2(0.125f * v0, 0.125f * v1);
                }
            }
        }
    }
}

// =================================================================
// fp16 attention helpers
// =================================================================
__device__ __forceinline__ void load_qf_h(unsigned qf[4][4], const __half* Qp,
                                          int r0, int tig) {
    #pragma unroll
    for (int ks = 0; ks < 4; ks++) {
        qf[ks][0] = *(const unsigned*)(Qp + (size_t)r0 * 512 + ks * 16 + 2 * tig);
        qf[ks][1] = *(const unsigned*)(Qp + (size_t)(r0 + 8) * 512 + ks * 16 + 2 * tig);
        qf[ks][2] = *(const unsigned*)(Qp + (size_t)r0 * 512 + ks * 16 + 8 + 2 * tig);
        qf[ks][3] = *(const unsigned*)(Qp + (size_t)(r0 + 8) * 512 + ks * 16 + 8 + 2 * tig);
    }
}
__device__ __forceinline__ void mma_S_h(float s[8][4], uint32_t Kb,
                                        const unsigned qf[4][4]) {
    #pragma unroll
    for (int jn = 0; jn < 8; jn++) { s[jn][0] = s[jn][1] = s[jn][2] = s[jn][3] = 0.f; }
    #pragma unroll
    for (int ks = 0; ks < 4; ks++)
        #pragma unroll
        for (int jp = 0; jp < 4; jp++) {
            unsigned b0, b1, b2, b3;
            ldsm4(b0, b1, b2, b3, Kb + jp * 2304 + ks * 32);
            unsigned bb0[2] = {b0, b1}, bb1[2] = {b2, b3};
            mma_f16(s[2 * jp], qf[ks], bb0);
            mma_f16(s[2 * jp + 1], qf[ks], bb1);
        }
}

// =================================================================
// Pass 1: online row max / sum over 1024 keys. grid = (4, 64, 4), 2-stage.
// =================================================================
__global__ __launch_bounds__(128, 4)
void flash_pass1(const __half* __restrict__ gq, const __half* __restrict__ gk,
                 float* __restrict__ ml)
{
    extern __shared__ char smc[];
    const uint32_t sb = (uint32_t)__cvta_generic_to_shared(smc);

    const int tid = threadIdx.x;
    const int w = tid >> 5, lane = tid & 31, g = lane >> 2, tig = lane & 3;
    const int z = blockIdx.y, b = z >> 3, h = z & 7;
    const int m0 = blockIdx.x * 64;
    const int qu = blockIdx.z;
    const __half* Qp = gq + ((size_t)(b * 256 + m0)) * 512 + h * 64;
    const __half* Kp = gk + (size_t)b * HW * 512 + h * 64 + (size_t)qu * 1024 * 512;
    const int r0 = w * 16 + g;
    const uint32_t koff = (uint32_t)((((lane >> 4) & 1) * 8 + (lane & 7)) * 144 +
                                     ((lane >> 3) & 1) * 16);

    unsigned qf[4][4];
    load_qf_h(qf, Qp, r0, tig);

    auto loadK = [&](int buf, int kt) {
        char* dst = smc + buf * 9216;
        const __half* src = Kp + (size_t)kt * 64 * 512;
        #pragma unroll
        for (int i = 0; i < 4; i++) {
            int id = tid + i * 128;
            int row = id >> 3, c8 = id & 7;
            cp16(dst + row * 144 + c8 * 16, src + (size_t)row * 512 + c8 * 8);
        }
    };

    float m[2] = {-1e30f, -1e30f}, l[2] = {0.f, 0.f};

    loadK(0, 0); cpcommit();
    for (int kt = 0; kt < 16; kt++) {
        const int buf = kt & 1;
        if (kt < 15) { loadK(buf ^ 1, kt + 1); cpcommit(); cpwait<1>(); }
        else cpwait<0>();
        __syncthreads();
        float s[8][4];
        mma_S_h(s, sb + buf * 9216 + koff, qf);
        #pragma unroll
        for (int rr = 0; rr < 2; rr++) {
            float mx = -1e30f;
            #pragma unroll
            for (int jn = 0; jn < 8; jn++)
                mx = fmaxf(mx, fmaxf(s[jn][2 * rr], s[jn][2 * rr + 1]));
            mx = fmaxf(mx, __shfl_xor_sync(0xffffffffu, mx, 1));
            mx = fmaxf(mx, __shfl_xor_sync(0xffffffffu, mx, 2));
            const float mn = fmaxf(m[rr], mx);
            float sum = 0.f;
            #pragma unroll
            for (int jn = 0; jn < 8; jn++)
                sum += __expf(s[jn][2 * rr] - mn) + __expf(s[jn][2 * rr + 1] - mn);
            sum += __shfl_xor_sync(0xffffffffu, sum, 1);
            sum += __shfl_xor_sync(0xffffffffu, sum, 2);
            l[rr] = l[rr] * __expf(m[rr] - mn) + sum;
            m[rr] = mn;
        }
        __syncthreads();
    }
    if (tig == 0) {
        float* dst = ml + (((size_t)(z * 4 + blockIdx.x) * NSPL + qu) * 64) * 2;
        dst[r0 * 2]           = m[0];
        dst[r0 * 2 + 1]       = l[0];
        dst[(r0 + 8) * 2]     = m[1];
        dst[(r0 + 8) * 2 + 1] = l[1];
    }
}

// =================================================================
// Pass 2: P = exp(S-m)/l -> attn; O += P @ V (fp16). grid = (4, 64, 4).
// =================================================================
__global__ __launch_bounds__(128, 3)
void flash_pass2(const __half* __restrict__ gq, const __half* __restrict__ gk,
                 const __half* __restrict__ gv, const float* __restrict__ ml,
                 float* __restrict__ attn, float* __restrict__ aop)
{
    extern __shared__ char smc[];
    const uint32_t sb = (uint32_t)__cvta_generic_to_shared(smc);

    const int tid = threadIdx.x;
    const int w = tid >> 5, lane = tid & 31, g = lane >> 2, tig = lane & 3;
    const int z = blockIdx.y, b = z >> 3, h = z & 7;
    const int m0 = blockIdx.x * 64;
    const int qu = blockIdx.z;
    const __half* Qp = gq + ((size_t)(b * 256 + m0)) * 512 + h * 64;
    const __half* Kp = gk + (size_t)b * HW * 512 + h * 64 + (size_t)qu * 1024 * 512;
    const __half* Vp = gv + (size_t)b * HW * 512 + h * 64 + (size_t)qu * 1024 * 512;
    float* Ap = attn + (size_t)z * NK * HW + (size_t)m0 * HW + qu * 1024;
    float* Op = aop + (size_t)qu * 2048 * 512 + ((size_t)(b * 256 + m0)) * 512 + h * 64;
    const int r0 = w * 16 + g;

    const uint32_t koff = (uint32_t)((((lane >> 4) & 1) * 8 + (lane & 7)) * 144 +
                                     ((lane >> 3) & 1) * 16);
    const uint32_t voff = (uint32_t)((((lane >> 3) & 1) * 8 + (lane & 7)) * 144 +
                                     ((lane >> 4) & 1) * 16);

    unsigned qf[4][4];
    load_qf_h(qf, Qp, r0, tig);

    float mg[2], invl[2];
    {
        const float* mlb = ml + ((size_t)(z * 4 + blockIdx.x) * NSPL) * 128;
        #pragma unroll
        for (int rr = 0; rr < 2; rr++) {
            const int row = r0 + rr * 8;
            float mm = -1e30f;
            #pragma unroll
            for (int q = 0; q < NSPL; q++) mm = fmaxf(mm, mlb[q * 128 + row * 2]);
            float ll = 0.f;
            #pragma unroll
            for (int q = 0; q < NSPL; q++)
                ll += mlb[q * 128 + row * 2 + 1] * __expf(mlb[q * 128 + row * 2] - mm);
            mg[rr] = mm;
            invl[rr] = 1.f / ll;
        }
    }

    auto loadK = [&](int buf, int kt) {
        char* dst = smc + buf * 9216;
        const __half* src = Kp + (size_t)kt * 64 * 512;
        #pragma unroll
        for (int i = 0; i < 4; i++) {
            int id = tid + i * 128;
            int row = id >> 3, c8 = id & 7;
            cp16(dst + row * 144 + c8 * 16, src + (size_t)row * 512 + c8 * 8);
        }
    };
    auto loadV = [&](int buf, int kt) {
        char* dst = smc + 2 * 9216 + buf * 9216;
        const __half* src = Vp + (size_t)kt * 64 * 512;
        #pragma unroll
        for (int i = 0; i < 4; i++) {
            int id = tid + i * 128;
            int row = id >> 3, c8 = id & 7;
            cp16(dst + row * 144 + c8 * 16, src + (size_t)row * 512 + c8 * 8);
        }
    };

    float o[8][4];
    #pragma unroll
    for (int jn = 0; jn < 8; jn++)
        #pragma unroll
        for (int r = 0; r < 4; r++) o[jn][r] = 0.f;

    loadK(0, 0); loadV(0, 0); cpcommit();
    for (int kt = 0; kt < 16; kt++) {
        const int buf = kt & 1;
        if (kt < 15) { loadK(buf ^ 1, kt + 1); loadV(buf ^ 1, kt + 1); cpcommit(); cpwait<1>(); }
        else cpwait<0>();
        __syncthreads();
        float s[8][4];
        mma_S_h(s, sb + buf * 9216 + koff, qf);

        unsigned ph[8][2];
        #pragma unroll
        for (int jn = 0; jn < 8; jn++) {
            const float p0 = __expf(s[jn][0] - mg[0]) * invl[0];
            const float p1 = __expf(s[jn][1] - mg[0]) * invl[0];
            const float p2 = __expf(s[jn][2] - mg[1]) * invl[1];
            const float p3 = __expf(s[jn][3] - mg[1]) * invl[1];
            const int col = jn * 8 + 2 * tig;
            *(float2*)(Ap + (size_t)r0 * HW + kt * 64 + col)       = make_float2(p0, p1);
            *(float2*)(Ap + (size_t)(r0 + 8) * HW + kt * 64 + col) = make_float2(p2, p3);
            ph[jn][0] = f2h2(p0, p1);
            ph[jn][1] = f2h2(p2, p3);
        }
        const uint32_t Vb = sb + 2 * 9216 + buf * 9216 + voff;
        #pragma unroll
        for (int ks = 0; ks < 4; ks++) {
            unsigned af[4] = {ph[2 * ks][0], ph[2 * ks][1],
                              ph[2 * ks + 1][0], ph[2 * ks + 1][1]};
            #pragma unroll
            for (int jp = 0; jp < 4; jp++) {
                unsigned v0, v1, v2, v3;
                ldsm4t(v0, v1, v2, v3, Vb + ks * 2304 + jp * 32);
                unsigned bb0[2] = {v0, v1}, bb1[2] = {v2, v3};
                mma_f16(o[2 * jp], af, bb0);
                mma_f16(o[2 * jp + 1], af, bb1);
            }
        }
        __syncthreads();
    }
    #pragma unroll
    for (int jn = 0; jn < 8; jn++) {
        const int col = jn * 8 + 2 * tig;
        *(float2*)(Op + (size_t)r0 * 512 + col)       = make_float2(o[jn][0], o[jn][1]);
        *(float2*)(Op + (size_t)(r0 + 8) * 512 + col) = make_float2(o[jn][2], o[jn][3]);
    }
}

// =================================================================
__global__ void add_ao(const float4* __restrict__ a, float4* __restrict__ c) {
    const int i = blockIdx.x * 512 + threadIdx.x;
    const size_t STRIDE = (size_t)2048 * 512 / 4;
    float4 x = a[i], y = a[i + STRIDE], zc = a[i + 2 * STRIDE], wd = a[i + 3 * STRIDE];
    c[i] = make_float4(rtf(x.x + y.x + zc.x + wd.x), rtf(x.y + y.y + zc.y + wd.y),
                       rtf(x.z + y.z + zc.z + wd.z), rtf(x.w + y.w + zc.w + wd.w));
}

// =================================================================
__global__ void ln_kernel(const float* __restrict__ x, const float* __restrict__ g,
                          const float* __restrict__ bb, float* __restrict__ out) {
    __shared__ float red[8];
    const int row = blockIdx.x, t = threadIdx.x;
    const float* xr = x + (size_t)row * 512;
    const float v0 = xr[t], v1 = xr[t + 256];
    float s = v0 + v1;
    #pragma unroll
    for (int o = 16; o; o >>= 1) s += __shfl_xor_sync(0xffffffffu, s, o);
    if ((t & 31) == 0) red[t >> 5] = s;
    __syncthreads();
    float tot = 0.f;
    #pragma unroll
    for (int i = 0; i < 8; i++) tot += red[i];
    const float mu = tot * (1.0f / 512.0f);
    const float d0 = v0 - mu, d1 = v1 - mu;
    float q = d0 * d0 + d1 * d1;
    __syncthreads();
    #pragma unroll
    for (int o = 16; o; o >>= 1) q += __shfl_xor_sync(0xffffffffu, q, o);
    if ((t & 31) == 0) red[t >> 5] = q;
    __syncthreads();
    tot = 0.f;
    #pragma unroll
    for (int i = 0; i < 8; i++) tot += red[i];
    const float inv = rsqrtf(tot * (1.0f / 512.0f) + 1e-5f);
    out[(size_t)row * 512 + t]       = d0 * inv * g[t] + bb[t];
    out[(size_t)row * 512 + t + 256] = d1 * inv * g[t + 256] + bb[t + 256];
}

// =================================================================
static const int SMEM_PROJ_N = (2 * 128 * 36 + 2 * 32 * 136) * 4;
static const int SMEM_KV = (2 * 32 * 136 + 2 * 32 * 72) * 4;   // 53248
static const int SMEM_P1 = 2 * 9216;
static const int SMEM_P2 = 4 * 9216;

extern "C" void kernel_launch(void* const* d_in, const int* in_sizes, int n_in,
                              void* d_out, int out_size) {
    const float* hidden = (const float*)d_in[0];
    const float* aux    = (const float*)d_in[1];
    const float* Wq = (const float*)d_in[2];
    const float* bq = (const float*)d_in[3];
    const float* Wk = (const float*)d_in[4];
    const float* bk = (const float*)d_in[5];
    const float* Wv = (const float*)d_in[6];
    const float* bv = (const float*)d_in[7];
    const float* Wo = (const float*)d_in[8];
    const float* bo = (const float*)d_in[9];
    const float* lng = (const float*)d_in[10];
    const float* lnb = (const float*)d_in[11];
    float* out = (float*)d_out;

    float *gauxp, *gwq, *gwo, *gwkv, *gbkv;
    float *gao, *gaop, *gx, *gml;
    __half *gq, *gk, *gv;
    cudaGetSymbolAddress((void**)&gauxp, g_auxp);
    cudaGetSymbolAddress((void**)&gwq,   g_wq);
    cudaGetSymbolAddress((void**)&gwo,   g_wo);
    cudaGetSymbolAddress((void**)&gwkv,  g_wkv);
    cudaGetSymbolAddress((void**)&gbkv,  g_bkv);
    cudaGetSymbolAddress((void**)&gq,    g_q);
    cudaGetSymbolAddress((void**)&gk,    g_k);
    cudaGetSymbolAddress((void**)&gv,    g_v);
    cudaGetSymbolAddress((void**)&gao,   g_ao);
    cudaGetSymbolAddress((void**)&gaop,  g_aop);
    cudaGetSymbolAddress((void**)&gx,    g_x);
    cudaGetSymbolAddress((void**)&gml,   g_ml);

    const size_t AUXOUT = (size_t)2048 * 512;
    const size_t ATTN_N = (size_t)64 * 256 * 4096;
    float* attn;
    if ((size_t)out_size >= AUXOUT + ATTN_N) attn = out + AUXOUT;
    else cudaGetSymbolAddress((void**)&attn, g_attn_fb);

    static cudaStream_t sQ = nullptr, sV = nullptr;
    static cudaEvent_t evPrep = nullptr, evQ = nullptr, evK = nullptr, evV = nullptr;
    if (!sQ) {
        cudaStreamCreateWithFlags(&sQ, cudaStreamNonBlocking);
        cudaStreamCreateWithFlags(&sV, cudaStreamNonBlocking);
        cudaEventCreateWithFlags(&evPrep, cudaEventDisableTiming);
        cudaEventCreateWithFlags(&evQ,    cudaEventDisableTiming);
        cudaEventCreateWithFlags(&evK,    cudaEventDisableTiming);
        cudaEventCreateWithFlags(&evV,    cudaEventDisableTiming);
        cudaFuncSetAttribute((const void*)gemm128ca<0>, cudaFuncAttributeMaxDynamicSharedMemorySize, SMEM_PROJ_N);
        cudaFuncSetAttribute((const void*)gemm128ca<2>, cudaFuncAttributeMaxDynamicSharedMemorySize, SMEM_PROJ_N);
        cudaFuncSetAttribute((const void*)gemm_kv,      cudaFuncAttributeMaxDynamicSharedMemorySize, SMEM_KV);
        cudaFuncSetAttribute((const void*)flash_pass1,  cudaFuncAttributeMaxDynamicSharedMemorySize, SMEM_P1);
        cudaFuncSetAttribute((const void*)flash_pass2,  cudaFuncAttributeMaxDynamicSharedMemorySize, SMEM_P2);
    }

    // prep small buffers
    prep_small<<<1025, 512>>>((const float4*)aux, (const float4*)Wq, (const float4*)Wo,
                              (const float4*)Wk, (const float4*)Wv,
                              (const float4*)bk, (const float4*)bv,
                              (float4*)gauxp, (float4*)gwq, (float4*)gwo,
                              (float4*)gwkv, (float4*)gbkv);
    cudaEventRecord(evPrep, 0);

    // Q projection on side stream (half output, 0.125 folded)
    cudaStreamWaitEvent(sQ, evPrep, 0);
    gemm128ca<2><<<dim3(4, 16), 128, SMEM_PROJ_N, sQ>>>(gauxp, gwq, bq, nullptr, (float*)gq);
    cudaEventRecord(evQ, sQ);

    // K projection (half output) on main stream
    gemm_kv<<<dim3(8, 256), 128, SMEM_KV>>>(hidden, gwkv, gbkv, gk, gv, 0);
    cudaEventRecord(evK, 0);

    // V projection on side stream (concurrent with pass1)
    cudaStreamWaitEvent(sV, evK, 0);
    gemm_kv<<<dim3(8, 256), 128, SMEM_KV, sV>>>(hidden, gwkv, gbkv, gk, gv, 512);
    cudaEventRecord(evV, sV);

    // pass1 on main (needs Q + K)
    cudaStreamWaitEvent(0, evQ, 0);
    flash_pass1<<<dim3(4, 64, NSPL), 128, SMEM_P1>>>(gq, gk, gml);

    // pass2 needs V as well
    cudaStreamWaitEvent(0, evV, 0);
    flash_pass2<<<dim3(4, 64, NSPL), 128, SMEM_P2>>>(gq, gk, gv, gml, attn, gaop);
    add_ao<<<512, 512>>>((const float4*)gaop, (float4*)gao);
    // out-proj + residual
    gemm128ca<0><<<dim3(4, 16), 128, SMEM_PROJ_N>>>(gao, gwo, bo, aux, gx);
    // LayerNorm
    ln_kernel<<<2048, 256>>>(gx, lng, lnb, out);
}

// round 15
// speedup vs baseline: 1.5535x; 1.5535x over previous
#include <cuda_runtime.h>
#include <cuda_fp16.h>
#include <cstddef>
#include <cstdint>

#define HW    4096
#define NK    256
#define DIM   512
#define NSPL  4   // key splits for attention

// ---------------- scratch (no allocation allowed) ----------------
__device__ float  g_auxp[2048u  * 512u];         // tf32-prepped aux
__device__ float  g_wq  [512u * 512u];
__device__ float  g_wo  [512u * 512u];
__device__ float  g_wkv [512u * 1024u];          // interleaved prepped Wk|Wv
__device__ float  g_bkv [1024u];
__device__ __half g_q [2048u  * 512u];           // half, 0.125 scale folded
__device__ __half g_k [32768u * 512u];           // half K
__device__ __half g_v [32768u * 512u];           // half V
__device__ float  g_aop[4u * 2048u * 512u];      // partial O per key-quarter
__device__ float  g_x [2048u  * 512u];
__device__ float  g_ml[64u * 4u * 4u * 64u * 2u];
__device__ float  g_attn_fb[(size_t)64 * 256 * 4096];

// ---------------- helpers ----------------
__device__ __forceinline__ unsigned f2tf(float x) {
    unsigned r;
    asm("cvt.rna.tf32.f32 %0, %1;" : "=r"(r) : "f"(x));
    return r;
}
__device__ __forceinline__ float rtf(float x) { return __uint_as_float(f2tf(x)); }
__device__ __forceinline__ unsigned f2h2(float a, float b) {
    __half2 h = __floats2half2_rn(a, b);
    return *(unsigned*)&h;
}
__device__ __forceinline__ void mma_tf32(float* c, const unsigned* a, const unsigned* b) {
    asm volatile(
        "mma.sync.aligned.m16n8k8.row.col.f32.tf32.tf32.f32 "
        "{%0,%1,%2,%3}, {%4,%5,%6,%7}, {%8,%9}, {%0,%1,%2,%3};\n"
        : "+f"(c[0]), "+f"(c[1]), "+f"(c[2]), "+f"(c[3])
        : "r"(a[0]), "r"(a[1]), "r"(a[2]), "r"(a[3]), "r"(b[0]), "r"(b[1]));
}
__device__ __forceinline__ void mma_f16(float* c, const unsigned* a, const unsigned* b) {
    asm volatile(
        "mma.sync.aligned.m16n8k16.row.col.f32.f16.f16.f32 "
        "{%0,%1,%2,%3}, {%4,%5,%6,%7}, {%8,%9}, {%0,%1,%2,%3};\n"
        : "+f"(c[0]), "+f"(c[1]), "+f"(c[2]), "+f"(c[3])
        : "r"(a[0]), "r"(a[1]), "r"(a[2]), "r"(a[3]), "r"(b[0]), "r"(b[1]));
}
__device__ __forceinline__ void ldsm4(unsigned& r0, unsigned& r1, unsigned& r2,
                                      unsigned& r3, uint32_t addr) {
    asm volatile("ldmatrix.sync.aligned.m8n8.x4.shared.b16 {%0,%1,%2,%3}, [%4];"
                 : "=r"(r0), "=r"(r1), "=r"(r2), "=r"(r3) : "r"(addr));
}
__device__ __forceinline__ void ldsm4t(unsigned& r0, unsigned& r1, unsigned& r2,
                                       unsigned& r3, uint32_t addr) {
    asm volatile("ldmatrix.sync.aligned.m8n8.x4.trans.shared.b16 {%0,%1,%2,%3}, [%4];"
                 : "=r"(r0), "=r"(r1), "=r"(r2), "=r"(r3) : "r"(addr));
}
__device__ __forceinline__ void cp16(void* dst, const void* src) {
    unsigned d = (unsigned)__cvta_generic_to_shared(dst);
    asm volatile("cp.async.cg.shared.global [%0], [%1], 16;" :: "r"(d), "l"(src));
}
__device__ __forceinline__ void cpcommit() { asm volatile("cp.async.commit_group;"); }
template<int N> __device__ __forceinline__ void cpwait() {
    asm volatile("cp.async.wait_group %0;" :: "n"(N));
}

// =================================================================
// Prep: tf32-round aux, Wq, Wo; build interleaved Wkv [512][1024] + bkv.
// segments (float4): aux 262144 | wq 65536 | wo 65536 | wkv 131072 | bkv 256
// =================================================================
__global__ void prep_small(const float4* __restrict__ aux,
                           const float4* __restrict__ wq, const float4* __restrict__ wo,
                           const float4* __restrict__ wk, const float4* __restrict__ wv,
                           const float4* __restrict__ bk, const float4* __restrict__ bv,
                           float4* __restrict__ auxp,
                           float4* __restrict__ pwq, float4* __restrict__ pwo,
                           float4* __restrict__ pwkv, float4* __restrict__ pbkv) {
    size_t i = (size_t)blockIdx.x * 512 + threadIdx.x;
    if (i >= 524544) return;
    const float4* s; float4* d;
    if (i < 262144)      { s = aux + i;           d = auxp + i; }
    else if (i < 327680) { s = wq + (i - 262144); d = pwq + (i - 262144); }
    else if (i < 393216) { s = wo + (i - 327680); d = pwo + (i - 327680); }
    else if (i < 524288) {
        size_t j = i - 393216;
        size_t row = j >> 8, c4 = j & 255;
        s = (c4 < 128) ? (wk + row * 128 + c4) : (wv + row * 128 + (c4 - 128));
        d = pwkv + j;
    } else {
        size_t j = i - 524288;
        s = (j < 128) ? (bk + j) : (bv + (j - 128));
        d = pbkv + j;
    }
    float4 v = *s;
    *d = make_float4(rtf(v.x), rtf(v.y), rtf(v.z), rtf(v.w));
}

// =================================================================
// K or V half projection (tf32 mma): [32768 x 512] = hidden @ Wkv half.
// 128x128 CTA, BK=32, 4 warps (2m x 2n) 64x64, occ 2, 2-stage.
// Output stored as __half. grid (4, 256). [R12 config — do not touch]
// =================================================================
__global__ __launch_bounds__(128, 2)
void gemm_kv(const float* __restrict__ A, const float* __restrict__ W,
             const float* __restrict__ bias,
             __half* __restrict__ gk, __half* __restrict__ gv, int jbase)
{
    extern __shared__ float sm[];
    float* Abase = sm;                       // [2][32][136]
    float* Bbase = sm + 2 * 32 * 136;        // [2][32][136]

    const int tid = threadIdx.x;
    const int m0 = blockIdx.y * 128, j0 = jbase + blockIdx.x * 128;
    const int w = tid >> 5, lane = tid & 31, g = lane >> 2, tig = lane & 3;
    const int mw = (w >> 1) * 64, nw = (w & 1) * 64;

    auto loadA = [&](int buf, int c0) {
        float* dst = Abase + buf * 32 * 136;
        const int bb = m0 >> 12, n0 = m0 & 4095;
        #pragma unroll
        for (int i = 0; i < 8; i++) {
            int id = tid + i * 128;
            int k = id >> 5, m4 = (id & 31) * 4;
            cp16(dst + k * 136 + m4, A + ((size_t)(bb * 512 + c0 + k)) * 4096 + n0 + m4);
        }
    };
    auto loadB = [&](int buf, int c0) {
        float* dst = Bbase + buf * 32 * 136;
        #pragma unroll
        for (int i = 0; i < 8; i++) {
            int id = tid + i * 128;
            int k = id >> 5, n4 = (id & 31) * 4;
            cp16(dst + k * 136 + n4, W + (size_t)(c0 + k) * 1024 + j0 + n4);
        }
    };

    float acc[4][8][4];
    #pragma unroll
    for (int i = 0; i < 4; i++)
        #pragma unroll
        for (int j = 0; j < 8; j++)
            #pragma unroll
            for (int r = 0; r < 4; r++) acc[i][j][r] = 0.f;

    loadA(0, 0); loadB(0, 0); cpcommit();
    for (int t = 0; t < 16; t++) {
        const int buf = t & 1;
        if (t < 15) { loadA(buf ^ 1, (t + 1) * 32); loadB(buf ^ 1, (t + 1) * 32); cpcommit(); cpwait<1>(); }
        else cpwait<0>();
        __syncthreads();
        const float* As = Abase + buf * 32 * 136;
        const float* Bs = Bbase + buf * 32 * 136;
        #pragma unroll
        for (int k8 = 0; k8 < 4; k8++) {
            const int kb = k8 * 8 + tig;
            unsigned af[4][4], bf[8][2];
            #pragma unroll
            for (int im = 0; im < 4; im++) {
                const int r = mw + im * 16 + g;
                af[im][0] = f2tf(As[kb * 136 + r]);
                af[im][1] = f2tf(As[kb * 136 + r + 8]);
                af[im][2] = f2tf(As[(kb + 4) * 136 + r]);
                af[im][3] = f2tf(As[(kb + 4) * 136 + r + 8]);
            }
            #pragma unroll
            for (int jn = 0; jn < 8; jn++) {
                const int n = nw + jn * 8 + g;
                bf[jn][0] = __float_as_uint(Bs[kb * 136 + n]);
                bf[jn][1] = __float_as_uint(Bs[(kb + 4) * 136 + n]);
            }
            #pragma unroll
            for (int im = 0; im < 4; im++)
                #pragma unroll
                for (int jn = 0; jn < 8; jn++)
                    mma_tf32(acc[im][jn], af[im], bf[jn]);
        }
        __syncthreads();
    }
    __half* Cout = (j0 < 512) ? gk : gv;
    const int jb = j0 & 511;
    #pragma unroll
    for (int im = 0; im < 4; im++) {
        #pragma unroll
        for (int jn = 0; jn < 8; jn++) {
            const int r0 = m0 + mw + im * 16 + g;
            const int col = nw + jn * 8 + 2 * tig;
            const float* cc = acc[im][jn];
            #pragma unroll
            for (int half = 0; half < 2; half++) {
                const int r = r0 + half * 8;
                float v0 = cc[half * 2]     + bias[j0 + col];
                float v1 = cc[half * 2 + 1] + bias[j0 + col + 1];
                *(unsigned*)(Cout + (size_t)r * 512 + jb + col) = f2h2(v0, v1);
            }
        }
    }
}

// =================================================================
// Q projection GEMM (tf32): half out with 0.125 scale. 128x128, occ 2.
// =================================================================
__global__ __launch_bounds__(128, 2)
void gemm_q(const float* __restrict__ A, const float* __restrict__ W,
            const float* __restrict__ bias, __half* __restrict__ C)
{
    extern __shared__ float sm[];
    float* Abase = sm;                   // [2][128][36]
    float* Bbase = sm + 2 * 128 * 36;    // [2][32][136]

    const int tid = threadIdx.x;
    const int m0 = blockIdx.y * 128, j0 = blockIdx.x * 128;
    const int w = tid >> 5, lane = tid & 31, g = lane >> 2, tig = lane & 3;
    const int mw = (w >> 1) * 64, nw = (w & 1) * 64;

    auto loadA = [&](int buf, int c0) {
        float* dst = Abase + buf * 128 * 36;
        #pragma unroll
        for (int i = 0; i < 8; i++) {
            int id = tid + i * 128;
            int m = id >> 3, c4 = (id & 7) * 4;
            cp16(dst + m * 36 + c4, A + (size_t)(m0 + m) * 512 + c0 + c4);
        }
    };
    auto loadB = [&](int buf, int c0) {
        float* dst = Bbase + buf * 32 * 136;
        #pragma unroll
        for (int i = 0; i < 8; i++) {
            int id = tid + i * 128;
            int k = id >> 5, n4 = (id & 31) * 4;
            cp16(dst + k * 136 + n4, W + (size_t)(c0 + k) * 512 + j0 + n4);
        }
    };

    float acc[4][8][4];
    #pragma unroll
    for (int i = 0; i < 4; i++)
        #pragma unroll
        for (int j = 0; j < 8; j++)
            #pragma unroll
            for (int r = 0; r < 4; r++) acc[i][j][r] = 0.f;

    loadA(0, 0); loadB(0, 0); cpcommit();
    for (int t = 0; t < 16; t++) {
        const int buf = t & 1;
        if (t < 15) { loadA(buf ^ 1, (t + 1) * 32); loadB(buf ^ 1, (t + 1) * 32); cpcommit(); cpwait<1>(); }
        else cpwait<0>();
        __syncthreads();
        const float* As = Abase + buf * 128 * 36;
        const float* Bs = Bbase + buf * 32 * 136;
        #pragma unroll
        for (int k8 = 0; k8 < 4; k8++) {
            const int kb = k8 * 8 + tig;
            unsigned af[4][4], bf[8][2];
            #pragma unroll
            for (int im = 0; im < 4; im++) {
                const int r = mw + im * 16 + g;
                af[im][0] = __float_as_uint(As[r * 36 + kb]);
                af[im][1] = __float_as_uint(As[(r + 8) * 36 + kb]);
                af[im][2] = __float_as_uint(As[r * 36 + kb + 4]);
                af[im][3] = __float_as_uint(As[(r + 8) * 36 + kb + 4]);
            }
            #pragma unroll
            for (int jn = 0; jn < 8; jn++) {
                const int n = nw + jn * 8 + g;
                bf[jn][0] = __float_as_uint(Bs[kb * 136 + n]);
                bf[jn][1] = __float_as_uint(Bs[(kb + 4) * 136 + n]);
            }
            #pragma unroll
            for (int im = 0; im < 4; im++)
                #pragma unroll
                for (int jn = 0; jn < 8; jn++)
                    mma_tf32(acc[im][jn], af[im], bf[jn]);
        }
        __syncthreads();
    }
    #pragma unroll
    for (int im = 0; im < 4; im++) {
        #pragma unroll
        for (int jn = 0; jn < 8; jn++) {
            const int r0 = m0 + mw + im * 16 + g;
            const int col = j0 + nw + jn * 8 + 2 * tig;
            const float* cc = acc[im][jn];
            #pragma unroll
            for (int half = 0; half < 2; half++) {
                const int r = r0 + half * 8;
                float v0 = cc[half * 2]     + bias[col];
                float v1 = cc[half * 2 + 1] + bias[col + 1];
                *(unsigned*)(C + (size_t)r * 512 + col) = f2h2(0.125f * v0, 0.125f * v1);
            }
        }
    }
}

// =================================================================
// Out projection, fused partial-O sum: x = (sum_q aop_q) @ Wo + bo + aux.
// 128x64 CTA tile, 4 warps (2m x 2n) 64x32, occ 3, grid (8, 16).
// A tiles: LDG 4 partials + sum + tf32-round -> smem. B: cp.async.
// =================================================================
__global__ __launch_bounds__(128, 3)
void gemm_out(const float* __restrict__ aop, const float* __restrict__ W,
              const float* __restrict__ bias, const float* __restrict__ resid,
              float* __restrict__ C)
{
    extern __shared__ float sm[];
    float* Abase = sm;                   // [2][128][36]
    float* Bbase = sm + 2 * 128 * 36;    // [2][32][72]
    const size_t STR = (size_t)2048 * 512;

    const int tid = threadIdx.x;
    const int m0 = blockIdx.y * 128, j0 = blockIdx.x * 64;
    const int w = tid >> 5, lane = tid & 31, g = lane >> 2, tig = lane & 3;
    const int mw = (w >> 1) * 64, nw = (w & 1) * 32;

    auto loadB = [&](int buf, int c0) {
        float* dst = Bbase + buf * 32 * 72;
        #pragma unroll
        for (int i = 0; i < 4; i++) {
            int id = tid + i * 128;
            int k = id >> 4, n4 = (id & 15) * 4;
            cp16(dst + k * 72 + n4, W + (size_t)(c0 + k) * 512 + j0 + n4);
        }
    };
    auto loadA = [&](int buf, int c0) {
        float* dst = Abase + buf * 128 * 36;
        #pragma unroll
        for (int i = 0; i < 8; i++) {
            int id = tid + i * 128;
            int m = id >> 3, c4 = (id & 7) * 4;
            const float* p = aop + (size_t)(m0 + m) * 512 + c0 + c4;
            float4 a = *(const float4*)p;
            float4 b = *(const float4*)(p + STR);
            float4 cc = *(const float4*)(p + 2 * STR);
            float4 dd = *(const float4*)(p + 3 * STR);
            float4 s;
            s.x = rtf(a.x + b.x + cc.x + dd.x);
            s.y = rtf(a.y + b.y + cc.y + dd.y);
            s.z = rtf(a.z + b.z + cc.z + dd.z);
            s.w = rtf(a.w + b.w + cc.w + dd.w);
            *(float4*)(dst + m * 36 + c4) = s;
        }
    };

    float acc[4][4][4];
    #pragma unroll
    for (int i = 0; i < 4; i++)
        #pragma unroll
        for (int j = 0; j < 4; j++)
            #pragma unroll
            for (int r = 0; r < 4; r++) acc[i][j][r] = 0.f;

    loadB(0, 0); cpcommit();
    loadA(0, 0);
    for (int t = 0; t < 16; t++) {
        const int buf = t & 1;
        if (t < 15) { loadB(buf ^ 1, (t + 1) * 32); cpcommit(); loadA(buf ^ 1, (t + 1) * 32); cpwait<1>(); }
        else cpwait<0>();
        __syncthreads();
        const float* As = Abase + buf * 128 * 36;
        const float* Bs = Bbase + buf * 32 * 72;
        #pragma unroll
        for (int k8 = 0; k8 < 4; k8++) {
            const int kb = k8 * 8 + tig;
            unsigned af[4][4], bf[4][2];
            #pragma unroll
            for (int im = 0; im < 4; im++) {
                const int r = mw + im * 16 + g;
                af[im][0] = __float_as_uint(As[r * 36 + kb]);
                af[im][1] = __float_as_uint(As[(r + 8) * 36 + kb]);
                af[im][2] = __float_as_uint(As[r * 36 + kb + 4]);
                af[im][3] = __float_as_uint(As[(r + 8) * 36 + kb + 4]);
            }
            #pragma unroll
            for (int jn = 0; jn < 4; jn++) {
                const int n = nw + jn * 8 + g;
                bf[jn][0] = __float_as_uint(Bs[kb * 72 + n]);
                bf[jn][1] = __float_as_uint(Bs[(kb + 4) * 72 + n]);
            }
            #pragma unroll
            for (int im = 0; im < 4; im++)
                #pragma unroll
                for (int jn = 0; jn < 4; jn++)
                    mma_tf32(acc[im][jn], af[im], bf[jn]);
        }
        __syncthreads();
    }
    #pragma unroll
    for (int im = 0; im < 4; im++) {
        #pragma unroll
        for (int jn = 0; jn < 4; jn++) {
            const int r0 = m0 + mw + im * 16 + g;
            const int col = j0 + nw + jn * 8 + 2 * tig;
            const float* cc = acc[im][jn];
            #pragma unroll
            for (int half = 0; half < 2; half++) {
                const int r = r0 + half * 8;
                float v0 = cc[half * 2]     + bias[col] + resid[(size_t)r * 512 + col];
                float v1 = cc[half * 2 + 1] + bias[col + 1] + resid[(size_t)r * 512 + col + 1];
                *(float2*)(C + (size_t)r * 512 + col) = make_float2(v0, v1);
            }
        }
    }
}

// =================================================================
// fp16 attention helpers
// =================================================================
__device__ __forceinline__ void load_qf_h(unsigned qf[4][4], const __half* Qp,
                                          int r0, int tig) {
    #pragma unroll
    for (int ks = 0; ks < 4; ks++) {
        qf[ks][0] = *(const unsigned*)(Qp + (size_t)r0 * 512 + ks * 16 + 2 * tig);
        qf[ks][1] = *(const unsigned*)(Qp + (size_t)(r0 + 8) * 512 + ks * 16 + 2 * tig);
        qf[ks][2] = *(const unsigned*)(Qp + (size_t)r0 * 512 + ks * 16 + 8 + 2 * tig);
        qf[ks][3] = *(const unsigned*)(Qp + (size_t)(r0 + 8) * 512 + ks * 16 + 8 + 2 * tig);
    }
}
__device__ __forceinline__ void mma_S_h(float s[8][4], uint32_t Kb,
                                        const unsigned qf[4][4]) {
    #pragma unroll
    for (int jn = 0; jn < 8; jn++) { s[jn][0] = s[jn][1] = s[jn][2] = s[jn][3] = 0.f; }
    #pragma unroll
    for (int ks = 0; ks < 4; ks++)
        #pragma unroll
        for (int jp = 0; jp < 4; jp++) {
            unsigned b0, b1, b2, b3;
            ldsm4(b0, b1, b2, b3, Kb + jp * 2304 + ks * 32);
            unsigned bb0[2] = {b0, b1}, bb1[2] = {b2, b3};
            mma_f16(s[2 * jp], qf[ks], bb0);
            mma_f16(s[2 * jp + 1], qf[ks], bb1);
        }
}

// =================================================================
// Pass 1: online row max / sum over 1024 keys. grid = (4, 64, 4), 2-stage.
// =================================================================
__global__ __launch_bounds__(128, 4)
void flash_pass1(const __half* __restrict__ gq, const __half* __restrict__ gk,
                 float* __restrict__ ml)
{
    extern __shared__ char smc[];
    const uint32_t sb = (uint32_t)__cvta_generic_to_shared(smc);

    const int tid = threadIdx.x;
    const int w = tid >> 5, lane = tid & 31, g = lane >> 2, tig = lane & 3;
    const int z = blockIdx.y, b = z >> 3, h = z & 7;
    const int m0 = blockIdx.x * 64;
    const int qu = blockIdx.z;
    const __half* Qp = gq + ((size_t)(b * 256 + m0)) * 512 + h * 64;
    const __half* Kp = gk + (size_t)b * HW * 512 + h * 64 + (size_t)qu * 1024 * 512;
    const int r0 = w * 16 + g;
    const uint32_t koff = (uint32_t)((((lane >> 4) & 1) * 8 + (lane & 7)) * 144 +
                                     ((lane >> 3) & 1) * 16);

    unsigned qf[4][4];
    load_qf_h(qf, Qp, r0, tig);

    auto loadK = [&](int buf, int kt) {
        char* dst = smc + buf * 9216;
        const __half* src = Kp + (size_t)kt * 64 * 512;
        #pragma unroll
        for (int i = 0; i < 4; i++) {
            int id = tid + i * 128;
            int row = id >> 3, c8 = id & 7;
            cp16(dst + row * 144 + c8 * 16, src + (size_t)row * 512 + c8 * 8);
        }
    };

    float m[2] = {-1e30f, -1e30f}, l[2] = {0.f, 0.f};

    loadK(0, 0); cpcommit();
    for (int kt = 0; kt < 16; kt++) {
        const int buf = kt & 1;
        if (kt < 15) { loadK(buf ^ 1, kt + 1); cpcommit(); cpwait<1>(); }
        else cpwait<0>();
        __syncthreads();
        float s[8][4];
        mma_S_h(s, sb + buf * 9216 + koff, qf);
        #pragma unroll
        for (int rr = 0; rr < 2; rr++) {
            float mx = -1e30f;
            #pragma unroll
            for (int jn = 0; jn < 8; jn++)
                mx = fmaxf(mx, fmaxf(s[jn][2 * rr], s[jn][2 * rr + 1]));
            mx = fmaxf(mx, __shfl_xor_sync(0xffffffffu, mx, 1));
            mx = fmaxf(mx, __shfl_xor_sync(0xffffffffu, mx, 2));
            const float mn = fmaxf(m[rr], mx);
            float sum = 0.f;
            #pragma unroll
            for (int jn = 0; jn < 8; jn++)
                sum += __expf(s[jn][2 * rr] - mn) + __expf(s[jn][2 * rr + 1] - mn);
            sum += __shfl_xor_sync(0xffffffffu, sum, 1);
            sum += __shfl_xor_sync(0xffffffffu, sum, 2);
            l[rr] = l[rr] * __expf(m[rr] - mn) + sum;
            m[rr] = mn;
        }
        __syncthreads();
    }
    if (tig == 0) {
        float* dst = ml + (((size_t)(z * 4 + blockIdx.x) * NSPL + qu) * 64) * 2;
        dst[r0 * 2]           = m[0];
        dst[r0 * 2 + 1]       = l[0];
        dst[(r0 + 8) * 2]     = m[1];
        dst[(r0 + 8) * 2 + 1] = l[1];
    }
}

// =================================================================
// Pass 2: P = exp(S-m)/l -> attn; O += P @ V (fp16). grid = (4, 64, 4).
// =================================================================
__global__ __launch_bounds__(128, 3)
void flash_pass2(const __half* __restrict__ gq, const __half* __restrict__ gk,
                 const __half* __restrict__ gv, const float* __restrict__ ml,
                 float* __restrict__ attn, float* __restrict__ aop)
{
    extern __shared__ char smc[];
    const uint32_t sb = (uint32_t)__cvta_generic_to_shared(smc);

    const int tid = threadIdx.x;
    const int w = tid >> 5, lane = tid & 31, g = lane >> 2, tig = lane & 3;
    const int z = blockIdx.y, b = z >> 3, h = z & 7;
    const int m0 = blockIdx.x * 64;
    const int qu = blockIdx.z;
    const __half* Qp = gq + ((size_t)(b * 256 + m0)) * 512 + h * 64;
    const __half* Kp = gk + (size_t)b * HW * 512 + h * 64 + (size_t)qu * 1024 * 512;
    const __half* Vp = gv + (size_t)b * HW * 512 + h * 64 + (size_t)qu * 1024 * 512;
    float* Ap = attn + (size_t)z * NK * HW + (size_t)m0 * HW + qu * 1024;
    float* Op = aop + (size_t)qu * 2048 * 512 + ((size_t)(b * 256 + m0)) * 512 + h * 64;
    const int r0 = w * 16 + g;

    const uint32_t koff = (uint32_t)((((lane >> 4) & 1) * 8 + (lane & 7)) * 144 +
                                     ((lane >> 3) & 1) * 16);
    const uint32_t voff = (uint32_t)((((lane >> 3) & 1) * 8 + (lane & 7)) * 144 +
                                     ((lane >> 4) & 1) * 16);

    unsigned qf[4][4];
    load_qf_h(qf, Qp, r0, tig);

    float mg[2], invl[2];
    {
        const float* mlb = ml + ((size_t)(z * 4 + blockIdx.x) * NSPL) * 128;
        #pragma unroll
        for (int rr = 0; rr < 2; rr++) {
            const int row = r0 + rr * 8;
            float mm = -1e30f;
            #pragma unroll
            for (int q = 0; q < NSPL; q++) mm = fmaxf(mm, mlb[q * 128 + row * 2]);
            float ll = 0.f;
            #pragma unroll
            for (int q = 0; q < NSPL; q++)
                ll += mlb[q * 128 + row * 2 + 1] * __expf(mlb[q * 128 + row * 2] - mm);
            mg[rr] = mm;
            invl[rr] = 1.f / ll;
        }
    }

    auto loadK = [&](int buf, int kt) {
        char* dst = smc + buf * 9216;
        const __half* src = Kp + (size_t)kt * 64 * 512;
        #pragma unroll
        for (int i = 0; i < 4; i++) {
            int id = tid + i * 128;
            int row = id >> 3, c8 = id & 7;
            cp16(dst + row * 144 + c8 * 16, src + (size_t)row * 512 + c8 * 8);
        }
    };
    auto loadV = [&](int buf, int kt) {
        char* dst = smc + 2 * 9216 + buf * 9216;
        const __half* src = Vp + (size_t)kt * 64 * 512;
        #pragma unroll
        for (int i = 0; i < 4; i++) {
            int id = tid + i * 128;
            int row = id >> 3, c8 = id & 7;
            cp16(dst + row * 144 + c8 * 16, src + (size_t)row * 512 + c8 * 8);
        }
    };

    float o[8][4];
    #pragma unroll
    for (int jn = 0; jn < 8; jn++)
        #pragma unroll
        for (int r = 0; r < 4; r++) o[jn][r] = 0.f;

    loadK(0, 0); loadV(0, 0); cpcommit();
    for (int kt = 0; kt < 16; kt++) {
        const int buf = kt & 1;
        if (kt < 15) { loadK(buf ^ 1, kt + 1); loadV(buf ^ 1, kt + 1); cpcommit(); cpwait<1>(); }
        else cpwait<0>();
        __syncthreads();
        float s[8][4];
        mma_S_h(s, sb + buf * 9216 + koff, qf);

        unsigned ph[8][2];
        #pragma unroll
        for (int jn = 0; jn < 8; jn++) {
            const float p0 = __expf(s[jn][0] - mg[0]) * invl[0];
            const float p1 = __expf(s[jn][1] - mg[0]) * invl[0];
            const float p2 = __expf(s[jn][2] - mg[1]) * invl[1];
            const float p3 = __expf(s[jn][3] - mg[1]) * invl[1];
            const int col = jn * 8 + 2 * tig;
            *(float2*)(Ap + (size_t)r0 * HW + kt * 64 + col)       = make_float2(p0, p1);
            *(float2*)(Ap + (size_t)(r0 + 8) * HW + kt * 64 + col) = make_float2(p2, p3);
            ph[jn][0] = f2h2(p0, p1);
            ph[jn][1] = f2h2(p2, p3);
        }
        const uint32_t Vb = sb + 2 * 9216 + buf * 9216 + voff;
        #pragma unroll
        for (int ks = 0; ks < 4; ks++) {
            unsigned af[4] = {ph[2 * ks][0], ph[2 * ks][1],
                              ph[2 * ks + 1][0], ph[2 * ks + 1][1]};
            #pragma unroll
            for (int jp = 0; jp < 4; jp++) {
                unsigned v0, v1, v2, v3;
                ldsm4t(v0, v1, v2, v3, Vb + ks * 2304 + jp * 32);
                unsigned bb0[2] = {v0, v1}, bb1[2] = {v2, v3};
                mma_f16(o[2 * jp], af, bb0);
                mma_f16(o[2 * jp + 1], af, bb1);
            }
        }
        __syncthreads();
    }
    #pragma unroll
    for (int jn = 0; jn < 8; jn++) {
        const int col = jn * 8 + 2 * tig;
        *(float2*)(Op + (size_t)r0 * 512 + col)       = make_float2(o[jn][0], o[jn][1]);
        *(float2*)(Op + (size_t)(r0 + 8) * 512 + col) = make_float2(o[jn][2], o[jn][3]);
    }
}

// =================================================================
__global__ void ln_kernel(const float* __restrict__ x, const float* __restrict__ g,
                          const float* __restrict__ bb, float* __restrict__ out) {
    __shared__ float red[8];
    const int row = blockIdx.x, t = threadIdx.x;
    const float* xr = x + (size_t)row * 512;
    const float v0 = xr[t], v1 = xr[t + 256];
    float s = v0 + v1;
    #pragma unroll
    for (int o = 16; o; o >>= 1) s += __shfl_xor_sync(0xffffffffu, s, o);
    if ((t & 31) == 0) red[t >> 5] = s;
    __syncthreads();
    float tot = 0.f;
    #pragma unroll
    for (int i = 0; i < 8; i++) tot += red[i];
    const float mu = tot * (1.0f / 512.0f);
    const float d0 = v0 - mu, d1 = v1 - mu;
    float q = d0 * d0 + d1 * d1;
    __syncthreads();
    #pragma unroll
    for (int o = 16; o; o >>= 1) q += __shfl_xor_sync(0xffffffffu, q, o);
    if ((t & 31) == 0) red[t >> 5] = q;
    __syncthreads();
    tot = 0.f;
    #pragma unroll
    for (int i = 0; i < 8; i++) tot += red[i];
    const float inv = rsqrtf(tot * (1.0f / 512.0f) + 1e-5f);
    out[(size_t)row * 512 + t]       = d0 * inv * g[t] + bb[t];
    out[(size_t)row * 512 + t + 256] = d1 * inv * g[t + 256] + bb[t + 256];
}

// =================================================================
static const int SMEM_PROJ_N = (2 * 128 * 36 + 2 * 32 * 136) * 4;
static const int SMEM_PROJ_H = (2 * 32 * 136 + 2 * 32 * 136) * 4;
static const int SMEM_OUT = (2 * 128 * 36 + 2 * 32 * 72) * 4;
static const int SMEM_P1 = 2 * 9216;
static const int SMEM_P2 = 4 * 9216;

extern "C" void kernel_launch(void* const* d_in, const int* in_sizes, int n_in,
                              void* d_out, int out_size) {
    const float* hidden = (const float*)d_in[0];
    const float* aux    = (const float*)d_in[1];
    const float* Wq = (const float*)d_in[2];
    const float* bq = (const float*)d_in[3];
    const float* Wk = (const float*)d_in[4];
    const float* bk = (const float*)d_in[5];
    const float* Wv = (const float*)d_in[6];
    const float* bv = (const float*)d_in[7];
    const float* Wo = (const float*)d_in[8];
    const float* bo = (const float*)d_in[9];
    const float* lng = (const float*)d_in[10];
    const float* lnb = (const float*)d_in[11];
    float* out = (float*)d_out;

    float *gauxp, *gwq, *gwo, *gwkv, *gbkv;
    float *gaop, *gx, *gml;
    __half *gq, *gk, *gv;
    cudaGetSymbolAddress((void**)&gauxp, g_auxp);
    cudaGetSymbolAddress((void**)&gwq,   g_wq);
    cudaGetSymbolAddress((void**)&gwo,   g_wo);
    cudaGetSymbolAddress((void**)&gwkv,  g_wkv);
    cudaGetSymbolAddress((void**)&gbkv,  g_bkv);
    cudaGetSymbolAddress((void**)&gq,    g_q);
    cudaGetSymbolAddress((void**)&gk,    g_k);
    cudaGetSymbolAddress((void**)&gv,    g_v);
    cudaGetSymbolAddress((void**)&gaop,  g_aop);
    cudaGetSymbolAddress((void**)&gx,    g_x);
    cudaGetSymbolAddress((void**)&gml,   g_ml);

    const size_t AUXOUT = (size_t)2048 * 512;
    const size_t ATTN_N = (size_t)64 * 256 * 4096;
    float* attn;
    if ((size_t)out_size >= AUXOUT + ATTN_N) attn = out + AUXOUT;
    else cudaGetSymbolAddress((void**)&attn, g_attn_fb);

    static cudaStream_t sQ = nullptr, sV = nullptr;
    static cudaEvent_t evPrep = nullptr, evQ = nullptr, evK = nullptr, evV = nullptr;
    if (!sQ) {
        cudaStreamCreateWithFlags(&sQ, cudaStreamNonBlocking);
        cudaStreamCreateWithFlags(&sV, cudaStreamNonBlocking);
        cudaEventCreateWithFlags(&evPrep, cudaEventDisableTiming);
        cudaEventCreateWithFlags(&evQ,    cudaEventDisableTiming);
        cudaEventCreateWithFlags(&evK,    cudaEventDisableTiming);
        cudaEventCreateWithFlags(&evV,    cudaEventDisableTiming);
        cudaFuncSetAttribute((const void*)gemm_q,      cudaFuncAttributeMaxDynamicSharedMemorySize, SMEM_PROJ_N);
        cudaFuncSetAttribute((const void*)gemm_out,    cudaFuncAttributeMaxDynamicSharedMemorySize, SMEM_OUT);
        cudaFuncSetAttribute((const void*)gemm_kv,     cudaFuncAttributeMaxDynamicSharedMemorySize, SMEM_PROJ_H);
        cudaFuncSetAttribute((const void*)flash_pass1, cudaFuncAttributeMaxDynamicSharedMemorySize, SMEM_P1);
        cudaFuncSetAttribute((const void*)flash_pass2, cudaFuncAttributeMaxDynamicSharedMemorySize, SMEM_P2);
    }

    // prep small buffers
    prep_small<<<1025, 512>>>((const float4*)aux, (const float4*)Wq, (const float4*)Wo,
                              (const float4*)Wk, (const float4*)Wv,
                              (const float4*)bk, (const float4*)bv,
                              (float4*)gauxp, (float4*)gwq, (float4*)gwo,
                              (float4*)gwkv, (float4*)gbkv);
    cudaEventRecord(evPrep, 0);

    // Q projection on side stream (half output, 0.125 folded)
    cudaStreamWaitEvent(sQ, evPrep, 0);
    gemm_q<<<dim3(4, 16), 128, SMEM_PROJ_N, sQ>>>(gauxp, gwq, bq, gq);
    cudaEventRecord(evQ, sQ);

    // K projection (half output) on main stream
    gemm_kv<<<dim3(4, 256), 128, SMEM_PROJ_H>>>(hidden, gwkv, gbkv, gk, gv, 0);
    cudaEventRecord(evK, 0);

    // V projection on side stream (concurrent with pass1)
    cudaStreamWaitEvent(sV, evK, 0);
    gemm_kv<<<dim3(4, 256), 128, SMEM_PROJ_H, sV>>>(hidden, gwkv, gbkv, gk, gv, 512);
    cudaEventRecord(evV, sV);

    // pass1 on main (needs Q + K)
    cudaStreamWaitEvent(0, evQ, 0);
    flash_pass1<<<dim3(4, 64, NSPL), 128, SMEM_P1>>>(gq, gk, gml);

    // pass2 needs V as well
    cudaStreamWaitEvent(0, evV, 0);
    flash_pass2<<<dim3(4, 64, NSPL), 128, SMEM_P2>>>(gq, gk, gv, gml, attn, gaop);

    // fused partial-sum + out-proj + residual
    gemm_out<<<dim3(8, 16), 128, SMEM_OUT>>>(gaop, gwo, bo, aux, gx);
    // LayerNorm
    ln_kernel<<<2048, 256>>>(gx, lng, lnb, out);
}

// round 16
// speedup vs baseline: 1.6625x; 1.0702x over previous
#include <cuda_runtime.h>
#include <cuda_fp16.h>
#include <cstddef>
#include <cstdint>

#define HW    4096
#define NK    256
#define DIM   512
#define NSPL  4   // key splits for attention

// ---------------- scratch (no allocation allowed) ----------------
__device__ float  g_auxp[2048u  * 512u];         // tf32-prepped aux
__device__ float  g_wq  [512u * 512u];
__device__ float  g_wo  [512u * 512u];
__device__ float  g_wkv [512u * 1024u];          // interleaved prepped Wk|Wv
__device__ float  g_bkv [1024u];
__device__ __half g_q [2048u  * 512u];           // half, 0.125 scale folded
__device__ __half g_k [32768u * 512u];           // half K
__device__ __half g_v [32768u * 512u];           // half V
__device__ float  g_ao [2048u * 512u];
__device__ float  g_aop[4u * 2048u * 512u];      // partial O per key-quarter
__device__ float  g_x [2048u  * 512u];
__device__ float  g_ml[64u * 4u * 4u * 64u * 2u];
__device__ float  g_attn_fb[(size_t)64 * 256 * 4096];

// ---------------- helpers ----------------
__device__ __forceinline__ unsigned f2tf(float x) {
    unsigned r;
    asm("cvt.rna.tf32.f32 %0, %1;" : "=r"(r) : "f"(x));
    return r;
}
__device__ __forceinline__ float rtf(float x) { return __uint_as_float(f2tf(x)); }
__device__ __forceinline__ unsigned f2h2(float a, float b) {
    __half2 h = __floats2half2_rn(a, b);
    return *(unsigned*)&h;
}
__device__ __forceinline__ void mma_tf32(float* c, const unsigned* a, const unsigned* b) {
    asm volatile(
        "mma.sync.aligned.m16n8k8.row.col.f32.tf32.tf32.f32 "
        "{%0,%1,%2,%3}, {%4,%5,%6,%7}, {%8,%9}, {%0,%1,%2,%3};\n"
        : "+f"(c[0]), "+f"(c[1]), "+f"(c[2]), "+f"(c[3])
        : "r"(a[0]), "r"(a[1]), "r"(a[2]), "r"(a[3]), "r"(b[0]), "r"(b[1]));
}
__device__ __forceinline__ void mma_f16(float* c, const unsigned* a, const unsigned* b) {
    asm volatile(
        "mma.sync.aligned.m16n8k16.row.col.f32.f16.f16.f32 "
        "{%0,%1,%2,%3}, {%4,%5,%6,%7}, {%8,%9}, {%0,%1,%2,%3};\n"
        : "+f"(c[0]), "+f"(c[1]), "+f"(c[2]), "+f"(c[3])
        : "r"(a[0]), "r"(a[1]), "r"(a[2]), "r"(a[3]), "r"(b[0]), "r"(b[1]));
}
__device__ __forceinline__ void ldsm4(unsigned& r0, unsigned& r1, unsigned& r2,
                                      unsigned& r3, uint32_t addr) {
    asm volatile("ldmatrix.sync.aligned.m8n8.x4.shared.b16 {%0,%1,%2,%3}, [%4];"
                 : "=r"(r0), "=r"(r1), "=r"(r2), "=r"(r3) : "r"(addr));
}
__device__ __forceinline__ void ldsm4t(unsigned& r0, unsigned& r1, unsigned& r2,
                                       unsigned& r3, uint32_t addr) {
    asm volatile("ldmatrix.sync.aligned.m8n8.x4.trans.shared.b16 {%0,%1,%2,%3}, [%4];"
                 : "=r"(r0), "=r"(r1), "=r"(r2), "=r"(r3) : "r"(addr));
}
__device__ __forceinline__ void cp16(void* dst, const void* src) {
    unsigned d = (unsigned)__cvta_generic_to_shared(dst);
    asm volatile("cp.async.cg.shared.global [%0], [%1], 16;" :: "r"(d), "l"(src));
}
__device__ __forceinline__ void cpcommit() { asm volatile("cp.async.commit_group;"); }
template<int N> __device__ __forceinline__ void cpwait() {
    asm volatile("cp.async.wait_group %0;" :: "n"(N));
}

// =================================================================
// Prep: tf32-round aux, Wq, Wo; build interleaved Wkv [512][1024] + bkv.
// =================================================================
__global__ void prep_small(const float4* __restrict__ aux,
                           const float4* __restrict__ wq, const float4* __restrict__ wo,
                           const float4* __restrict__ wk, const float4* __restrict__ wv,
                           const float4* __restrict__ bk, const float4* __restrict__ bv,
                           float4* __restrict__ auxp,
                           float4* __restrict__ pwq, float4* __restrict__ pwo,
                           float4* __restrict__ pwkv, float4* __restrict__ pbkv) {
    size_t i = (size_t)blockIdx.x * 512 + threadIdx.x;
    if (i >= 524544) return;
    const float4* s; float4* d;
    if (i < 262144)      { s = aux + i;           d = auxp + i; }
    else if (i < 327680) { s = wq + (i - 262144); d = pwq + (i - 262144); }
    else if (i < 393216) { s = wo + (i - 327680); d = pwo + (i - 327680); }
    else if (i < 524288) {
        size_t j = i - 393216;
        size_t row = j >> 8, c4 = j & 255;
        s = (c4 < 128) ? (wk + row * 128 + c4) : (wv + row * 128 + (c4 - 128));
        d = pwkv + j;
    } else {
        size_t j = i - 524288;
        s = (j < 128) ? (bk + j) : (bv + (j - 128));
        d = pbkv + j;
    }
    float4 v = *s;
    *d = make_float4(rtf(v.x), rtf(v.y), rtf(v.z), rtf(v.w));
}

// =================================================================
// K or V half projection (tf32 mma): [32768 x 512] = hidden @ Wkv half.
// 128x128 CTA, BK=32, 4 warps (2m x 2n) 64x64, occ 2, 2-stage. Half out.
// [R12 config — local optimum, do not touch]
// =================================================================
__global__ __launch_bounds__(128, 2)
void gemm_kv(const float* __restrict__ A, const float* __restrict__ W,
             const float* __restrict__ bias,
             __half* __restrict__ gk, __half* __restrict__ gv, int jbase)
{
    extern __shared__ float sm[];
    float* Abase = sm;                       // [2][32][136]
    float* Bbase = sm + 2 * 32 * 136;        // [2][32][136]

    const int tid = threadIdx.x;
    const int m0 = blockIdx.y * 128, j0 = jbase + blockIdx.x * 128;
    const int w = tid >> 5, lane = tid & 31, g = lane >> 2, tig = lane & 3;
    const int mw = (w >> 1) * 64, nw = (w & 1) * 64;

    auto loadA = [&](int buf, int c0) {
        float* dst = Abase + buf * 32 * 136;
        const int bb = m0 >> 12, n0 = m0 & 4095;
        #pragma unroll
        for (int i = 0; i < 8; i++) {
            int id = tid + i * 128;
            int k = id >> 5, m4 = (id & 31) * 4;
            cp16(dst + k * 136 + m4, A + ((size_t)(bb * 512 + c0 + k)) * 4096 + n0 + m4);
        }
    };
    auto loadB = [&](int buf, int c0) {
        float* dst = Bbase + buf * 32 * 136;
        #pragma unroll
        for (int i = 0; i < 8; i++) {
            int id = tid + i * 128;
            int k = id >> 5, n4 = (id & 31) * 4;
            cp16(dst + k * 136 + n4, W + (size_t)(c0 + k) * 1024 + j0 + n4);
        }
    };

    float acc[4][8][4];
    #pragma unroll
    for (int i = 0; i < 4; i++)
        #pragma unroll
        for (int j = 0; j < 8; j++)
            #pragma unroll
            for (int r = 0; r < 4; r++) acc[i][j][r] = 0.f;

    loadA(0, 0); loadB(0, 0); cpcommit();
    for (int t = 0; t < 16; t++) {
        const int buf = t & 1;
        if (t < 15) { loadA(buf ^ 1, (t + 1) * 32); loadB(buf ^ 1, (t + 1) * 32); cpcommit(); cpwait<1>(); }
        else cpwait<0>();
        __syncthreads();
        const float* As = Abase + buf * 32 * 136;
        const float* Bs = Bbase + buf * 32 * 136;
        #pragma unroll
        for (int k8 = 0; k8 < 4; k8++) {
            const int kb = k8 * 8 + tig;
            unsigned af[4][4], bf[8][2];
            #pragma unroll
            for (int im = 0; im < 4; im++) {
                const int r = mw + im * 16 + g;
                af[im][0] = f2tf(As[kb * 136 + r]);
                af[im][1] = f2tf(As[kb * 136 + r + 8]);
                af[im][2] = f2tf(As[(kb + 4) * 136 + r]);
                af[im][3] = f2tf(As[(kb + 4) * 136 + r + 8]);
            }
            #pragma unroll
            for (int jn = 0; jn < 8; jn++) {
                const int n = nw + jn * 8 + g;
                bf[jn][0] = __float_as_uint(Bs[kb * 136 + n]);
                bf[jn][1] = __float_as_uint(Bs[(kb + 4) * 136 + n]);
            }
            #pragma unroll
            for (int im = 0; im < 4; im++)
                #pragma unroll
                for (int jn = 0; jn < 8; jn++)
                    mma_tf32(acc[im][jn], af[im], bf[jn]);
        }
        __syncthreads();
    }
    __half* Cout = (j0 < 512) ? gk : gv;
    const int jb = j0 & 511;
    #pragma unroll
    for (int im = 0; im < 4; im++) {
        #pragma unroll
        for (int jn = 0; jn < 8; jn++) {
            const int r0 = m0 + mw + im * 16 + g;
            const int col = nw + jn * 8 + 2 * tig;
            const float* cc = acc[im][jn];
            #pragma unroll
            for (int half = 0; half < 2; half++) {
                const int r = r0 + half * 8;
                float v0 = cc[half * 2]     + bias[j0 + col];
                float v1 = cc[half * 2 + 1] + bias[j0 + col + 1];
                *(unsigned*)(Cout + (size_t)r * 512 + jb + col) = f2h2(v0, v1);
            }
        }
    }
}

// =================================================================
// Small projection GEMM (tf32). MODE 0: fp32 out (+resid);
// MODE 2: half out with 0.125 scale (Q projection).
// =================================================================
template<int MODE>
__global__ __launch_bounds__(128, 2)
void gemm128ca(const float* __restrict__ A, const float* __restrict__ W,
               const float* __restrict__ bias, const float* __restrict__ resid,
               float* __restrict__ C)
{
    extern __shared__ float sm[];
    float* Abase = sm;                   // [2][128][36]
    float* Bbase = sm + 2 * 128 * 36;    // [2][32][136]

    const int tid = threadIdx.x;
    const int m0 = blockIdx.y * 128, j0 = blockIdx.x * 128;
    const int w = tid >> 5, lane = tid & 31, g = lane >> 2, tig = lane & 3;
    const int mw = (w >> 1) * 64, nw = (w & 1) * 64;

    auto loadA = [&](int buf, int c0) {
        float* dst = Abase + buf * 128 * 36;
        #pragma unroll
        for (int i = 0; i < 8; i++) {
            int id = tid + i * 128;
            int m = id >> 3, c4 = (id & 7) * 4;
            cp16(dst + m * 36 + c4, A + (size_t)(m0 + m) * 512 + c0 + c4);
        }
    };
    auto loadB = [&](int buf, int c0) {
        float* dst = Bbase + buf * 32 * 136;
        #pragma unroll
        for (int i = 0; i < 8; i++) {
            int id = tid + i * 128;
            int k = id >> 5, n4 = (id & 31) * 4;
            cp16(dst + k * 136 + n4, W + (size_t)(c0 + k) * 512 + j0 + n4);
        }
    };

    float acc[4][8][4];
    #pragma unroll
    for (int i = 0; i < 4; i++)
        #pragma unroll
        for (int j = 0; j < 8; j++)
            #pragma unroll
            for (int r = 0; r < 4; r++) acc[i][j][r] = 0.f;

    loadA(0, 0); loadB(0, 0); cpcommit();
    for (int t = 0; t < 16; t++) {
        const int buf = t & 1;
        if (t < 15) { loadA(buf ^ 1, (t + 1) * 32); loadB(buf ^ 1, (t + 1) * 32); cpcommit(); cpwait<1>(); }
        else cpwait<0>();
        __syncthreads();
        const float* As = Abase + buf * 128 * 36;
        const float* Bs = Bbase + buf * 32 * 136;
        #pragma unroll
        for (int k8 = 0; k8 < 4; k8++) {
            const int kb = k8 * 8 + tig;
            unsigned af[4][4], bf[8][2];
            #pragma unroll
            for (int im = 0; im < 4; im++) {
                const int r = mw + im * 16 + g;
                af[im][0] = __float_as_uint(As[r * 36 + kb]);
                af[im][1] = __float_as_uint(As[(r + 8) * 36 + kb]);
                af[im][2] = __float_as_uint(As[r * 36 + kb + 4]);
                af[im][3] = __float_as_uint(As[(r + 8) * 36 + kb + 4]);
            }
            #pragma unroll
            for (int jn = 0; jn < 8; jn++) {
                const int n = nw + jn * 8 + g;
                bf[jn][0] = __float_as_uint(Bs[kb * 136 + n]);
                bf[jn][1] = __float_as_uint(Bs[(kb + 4) * 136 + n]);
            }
            #pragma unroll
            for (int im = 0; im < 4; im++)
                #pragma unroll
                for (int jn = 0; jn < 8; jn++)
                    mma_tf32(acc[im][jn], af[im], bf[jn]);
        }
        __syncthreads();
    }
    #pragma unroll
    for (int im = 0; im < 4; im++) {
        #pragma unroll
        for (int jn = 0; jn < 8; jn++) {
            const int r0 = m0 + mw + im * 16 + g;
            const int col = j0 + nw + jn * 8 + 2 * tig;
            const float* cc = acc[im][jn];
            #pragma unroll
            for (int half = 0; half < 2; half++) {
                const int r = r0 + half * 8;
                float v0 = cc[half * 2]     + bias[col];
                float v1 = cc[half * 2 + 1] + bias[col + 1];
                if (MODE == 0) {
                    if (resid) {
                        v0 += resid[(size_t)r * 512 + col];
                        v1 += resid[(size_t)r * 512 + col + 1];
                    }
                    *(float2*)(C + (size_t)r * 512 + col) = make_float2(v0, v1);
                } else {
                    __half* Ch = (__half*)C;
                    *(unsigned*)(Ch + (size_t)r * 512 + col) = f2h2(0.125f * v0, 0.125f * v1);
                }
            }
        }
    }
}

// =================================================================
// fp16 attention helpers
// =================================================================
__device__ __forceinline__ void load_qf_h(unsigned qf[4][4], const __half* Qp,
                                          int r0, int tig) {
    #pragma unroll
    for (int ks = 0; ks < 4; ks++) {
        qf[ks][0] = *(const unsigned*)(Qp + (size_t)r0 * 512 + ks * 16 + 2 * tig);
        qf[ks][1] = *(const unsigned*)(Qp + (size_t)(r0 + 8) * 512 + ks * 16 + 2 * tig);
        qf[ks][2] = *(const unsigned*)(Qp + (size_t)r0 * 512 + ks * 16 + 8 + 2 * tig);
        qf[ks][3] = *(const unsigned*)(Qp + (size_t)(r0 + 8) * 512 + ks * 16 + 8 + 2 * tig);
    }
}
__device__ __forceinline__ void mma_S_h(float s[8][4], uint32_t Kb,
                                        const unsigned qf[4][4]) {
    #pragma unroll
    for (int jn = 0; jn < 8; jn++) { s[jn][0] = s[jn][1] = s[jn][2] = s[jn][3] = 0.f; }
    #pragma unroll
    for (int ks = 0; ks < 4; ks++)
        #pragma unroll
        for (int jp = 0; jp < 4; jp++) {
            unsigned b0, b1, b2, b3;
            ldsm4(b0, b1, b2, b3, Kb + jp * 2304 + ks * 32);
            unsigned bb0[2] = {b0, b1}, bb1[2] = {b2, b3};
            mma_f16(s[2 * jp], qf[ks], bb0);
            mma_f16(s[2 * jp + 1], qf[ks], bb1);
        }
}

// =================================================================
// Pass 1: online row max / sum over 1024 keys. grid = (4, 64, 4), 2-stage.
// =================================================================
__global__ __launch_bounds__(128, 4)
void flash_pass1(const __half* __restrict__ gq, const __half* __restrict__ gk,
                 float* __restrict__ ml)
{
    extern __shared__ char smc[];
    const uint32_t sb = (uint32_t)__cvta_generic_to_shared(smc);

    const int tid = threadIdx.x;
    const int w = tid >> 5, lane = tid & 31, g = lane >> 2, tig = lane & 3;
    const int z = blockIdx.y, b = z >> 3, h = z & 7;
    const int m0 = blockIdx.x * 64;
    const int qu = blockIdx.z;
    const __half* Qp = gq + ((size_t)(b * 256 + m0)) * 512 + h * 64;
    const __half* Kp = gk + (size_t)b * HW * 512 + h * 64 + (size_t)qu * 1024 * 512;
    const int r0 = w * 16 + g;
    const uint32_t koff = (uint32_t)((((lane >> 4) & 1) * 8 + (lane & 7)) * 144 +
                                     ((lane >> 3) & 1) * 16);

    unsigned qf[4][4];
    load_qf_h(qf, Qp, r0, tig);

    auto loadK = [&](int buf, int kt) {
        char* dst = smc + buf * 9216;
        const __half* src = Kp + (size_t)kt * 64 * 512;
        #pragma unroll
        for (int i = 0; i < 4; i++) {
            int id = tid + i * 128;
            int row = id >> 3, c8 = id & 7;
            cp16(dst + row * 144 + c8 * 16, src + (size_t)row * 512 + c8 * 8);
        }
    };

    float m[2] = {-1e30f, -1e30f}, l[2] = {0.f, 0.f};

    loadK(0, 0); cpcommit();
    for (int kt = 0; kt < 16; kt++) {
        const int buf = kt & 1;
        if (kt < 15) { loadK(buf ^ 1, kt + 1); cpcommit(); cpwait<1>(); }
        else cpwait<0>();
        __syncthreads();
        float s[8][4];
        mma_S_h(s, sb + buf * 9216 + koff, qf);
        #pragma unroll
        for (int rr = 0; rr < 2; rr++) {
            float mx = -1e30f;
            #pragma unroll
            for (int jn = 0; jn < 8; jn++)
                mx = fmaxf(mx, fmaxf(s[jn][2 * rr], s[jn][2 * rr + 1]));
            mx = fmaxf(mx, __shfl_xor_sync(0xffffffffu, mx, 1));
            mx = fmaxf(mx, __shfl_xor_sync(0xffffffffu, mx, 2));
            const float mn = fmaxf(m[rr], mx);
            float sum = 0.f;
            #pragma unroll
            for (int jn = 0; jn < 8; jn++)
                sum += __expf(s[jn][2 * rr] - mn) + __expf(s[jn][2 * rr + 1] - mn);
            sum += __shfl_xor_sync(0xffffffffu, sum, 1);
            sum += __shfl_xor_sync(0xffffffffu, sum, 2);
            l[rr] = l[rr] * __expf(m[rr] - mn) + sum;
            m[rr] = mn;
        }
        __syncthreads();
    }
    if (tig == 0) {
        float* dst = ml + (((size_t)(z * 4 + blockIdx.x) * NSPL + qu) * 64) * 2;
        dst[r0 * 2]           = m[0];
        dst[r0 * 2 + 1]       = l[0];
        dst[(r0 + 8) * 2]     = m[1];
        dst[(r0 + 8) * 2 + 1] = l[1];
    }
}

// =================================================================
// Pass 2: P = exp(S-m)/l -> attn; O += P @ V (fp16). grid = (4, 64, 4).
// occ 4 (regs ~112 < 128 cap — no spills expected).
// =================================================================
__global__ __launch_bounds__(128, 4)
void flash_pass2(const __half* __restrict__ gq, const __half* __restrict__ gk,
                 const __half* __restrict__ gv, const float* __restrict__ ml,
                 float* __restrict__ attn, float* __restrict__ aop)
{
    extern __shared__ char smc[];
    const uint32_t sb = (uint32_t)__cvta_generic_to_shared(smc);

    const int tid = threadIdx.x;
    const int w = tid >> 5, lane = tid & 31, g = lane >> 2, tig = lane & 3;
    const int z = blockIdx.y, b = z >> 3, h = z & 7;
    const int m0 = blockIdx.x * 64;
    const int qu = blockIdx.z;
    const __half* Qp = gq + ((size_t)(b * 256 + m0)) * 512 + h * 64;
    const __half* Kp = gk + (size_t)b * HW * 512 + h * 64 + (size_t)qu * 1024 * 512;
    const __half* Vp = gv + (size_t)b * HW * 512 + h * 64 + (size_t)qu * 1024 * 512;
    float* Ap = attn + (size_t)z * NK * HW + (size_t)m0 * HW + qu * 1024;
    float* Op = aop + (size_t)qu * 2048 * 512 + ((size_t)(b * 256 + m0)) * 512 + h * 64;
    const int r0 = w * 16 + g;

    const uint32_t koff = (uint32_t)((((lane >> 4) & 1) * 8 + (lane & 7)) * 144 +
                                     ((lane >> 3) & 1) * 16);
    const uint32_t voff = (uint32_t)((((lane >> 3) & 1) * 8 + (lane & 7)) * 144 +
                                     ((lane >> 4) & 1) * 16);

    unsigned qf[4][4];
    load_qf_h(qf, Qp, r0, tig);

    float mg[2], invl[2];
    {
        const float* mlb = ml + ((size_t)(z * 4 + blockIdx.x) * NSPL) * 128;
        #pragma unroll
        for (int rr = 0; rr < 2; rr++) {
            const int row = r0 + rr * 8;
            float mm = -1e30f;
            #pragma unroll
            for (int q = 0; q < NSPL; q++) mm = fmaxf(mm, mlb[q * 128 + row * 2]);
            float ll = 0.f;
            #pragma unroll
            for (int q = 0; q < NSPL; q++)
                ll += mlb[q * 128 + row * 2 + 1] * __expf(mlb[q * 128 + row * 2] - mm);
            mg[rr] = mm;
            invl[rr] = 1.f / ll;
        }
    }

    auto loadK = [&](int buf, int kt) {
        char* dst = smc + buf * 9216;
        const __half* src = Kp + (size_t)kt * 64 * 512;
        #pragma unroll
        for (int i = 0; i < 4; i++) {
            int id = tid + i * 128;
            int row = id >> 3, c8 = id & 7;
            cp16(dst + row * 144 + c8 * 16, src + (size_t)row * 512 + c8 * 8);
        }
    };
    auto loadV = [&](int buf, int kt) {
        char* dst = smc + 2 * 9216 + buf * 9216;
        const __half* src = Vp + (size_t)kt * 64 * 512;
        #pragma unroll
        for (int i = 0; i < 4; i++) {
            int id = tid + i * 128;
            int row = id >> 3, c8 = id & 7;
            cp16(dst + row * 144 + c8 * 16, src + (size_t)row * 512 + c8 * 8);
        }
    };

    float o[8][4];
    #pragma unroll
    for (int jn = 0; jn < 8; jn++)
        #pragma unroll
        for (int r = 0; r < 4; r++) o[jn][r] = 0.f;

    loadK(0, 0); loadV(0, 0); cpcommit();
    for (int kt = 0; kt < 16; kt++) {
        const int buf = kt & 1;
        if (kt < 15) { loadK(buf ^ 1, kt + 1); loadV(buf ^ 1, kt + 1); cpcommit(); cpwait<1>(); }
        else cpwait<0>();
        __syncthreads();
        float s[8][4];
        mma_S_h(s, sb + buf * 9216 + koff, qf);

        unsigned ph[8][2];
        #pragma unroll
        for (int jn = 0; jn < 8; jn++) {
            const float p0 = __expf(s[jn][0] - mg[0]) * invl[0];
            const float p1 = __expf(s[jn][1] - mg[0]) * invl[0];
            const float p2 = __expf(s[jn][2] - mg[1]) * invl[1];
            const float p3 = __expf(s[jn][3] - mg[1]) * invl[1];
            const int col = jn * 8 + 2 * tig;
            *(float2*)(Ap + (size_t)r0 * HW + kt * 64 + col)       = make_float2(p0, p1);
            *(float2*)(Ap + (size_t)(r0 + 8) * HW + kt * 64 + col) = make_float2(p2, p3);
            ph[jn][0] = f2h2(p0, p1);
            ph[jn][1] = f2h2(p2, p3);
        }
        const uint32_t Vb = sb + 2 * 9216 + buf * 9216 + voff;
        #pragma unroll
        for (int ks = 0; ks < 4; ks++) {
            unsigned af[4] = {ph[2 * ks][0], ph[2 * ks][1],
                              ph[2 * ks + 1][0], ph[2 * ks + 1][1]};
            #pragma unroll
            for (int jp = 0; jp < 4; jp++) {
                unsigned v0, v1, v2, v3;
                ldsm4t(v0, v1, v2, v3, Vb + ks * 2304 + jp * 32);
                unsigned bb0[2] = {v0, v1}, bb1[2] = {v2, v3};
                mma_f16(o[2 * jp], af, bb0);
                mma_f16(o[2 * jp + 1], af, bb1);
            }
        }
        __syncthreads();
    }
    #pragma unroll
    for (int jn = 0; jn < 8; jn++) {
        const int col = jn * 8 + 2 * tig;
        *(float2*)(Op + (size_t)r0 * 512 + col)       = make_float2(o[jn][0], o[jn][1]);
        *(float2*)(Op + (size_t)(r0 + 8) * 512 + col) = make_float2(o[jn][2], o[jn][3]);
    }
}

// =================================================================
__global__ void add_ao(const float4* __restrict__ a, float4* __restrict__ c) {
    const int i = blockIdx.x * 512 + threadIdx.x;
    const size_t STRIDE = (size_t)2048 * 512 / 4;
    float4 x = a[i], y = a[i + STRIDE], zc = a[i + 2 * STRIDE], wd = a[i + 3 * STRIDE];
    c[i] = make_float4(rtf(x.x + y.x + zc.x + wd.x), rtf(x.y + y.y + zc.y + wd.y),
                       rtf(x.z + y.z + zc.z + wd.z), rtf(x.w + y.w + zc.w + wd.w));
}

// =================================================================
__global__ void ln_kernel(const float* __restrict__ x, const float* __restrict__ g,
                          const float* __restrict__ bb, float* __restrict__ out) {
    __shared__ float red[8];
    const int row = blockIdx.x, t = threadIdx.x;
    const float* xr = x + (size_t)row * 512;
    const float v0 = xr[t], v1 = xr[t + 256];
    float s = v0 + v1;
    #pragma unroll
    for (int o = 16; o; o >>= 1) s += __shfl_xor_sync(0xffffffffu, s, o);
    if ((t & 31) == 0) red[t >> 5] = s;
    __syncthreads();
    float tot = 0.f;
    #pragma unroll
    for (int i = 0; i < 8; i++) tot += red[i];
    const float mu = tot * (1.0f / 512.0f);
    const float d0 = v0 - mu, d1 = v1 - mu;
    float q = d0 * d0 + d1 * d1;
    __syncthreads();
    #pragma unroll
    for (int o = 16; o; o >>= 1) q += __shfl_xor_sync(0xffffffffu, q, o);
    if ((t & 31) == 0) red[t >> 5] = q;
    __syncthreads();
    tot = 0.f;
    #pragma unroll
    for (int i = 0; i < 8; i++) tot += red[i];
    const float inv = rsqrtf(tot * (1.0f / 512.0f) + 1e-5f);
    out[(size_t)row * 512 + t]       = d0 * inv * g[t] + bb[t];
    out[(size_t)row * 512 + t + 256] = d1 * inv * g[t + 256] + bb[t + 256];
}

// =================================================================
static const int SMEM_PROJ_N = (2 * 128 * 36 + 2 * 32 * 136) * 4;
static const int SMEM_PROJ_H = (2 * 32 * 136 + 2 * 32 * 136) * 4;
static const int SMEM_P1 = 2 * 9216;
static const int SMEM_P2 = 4 * 9216;

extern "C" void kernel_launch(void* const* d_in, const int* in_sizes, int n_in,
                              void* d_out, int out_size) {
    const float* hidden = (const float*)d_in[0];
    const float* aux    = (const float*)d_in[1];
    const float* Wq = (const float*)d_in[2];
    const float* bq = (const float*)d_in[3];
    const float* Wk = (const float*)d_in[4];
    const float* bk = (const float*)d_in[5];
    const float* Wv = (const float*)d_in[6];
    const float* bv = (const float*)d_in[7];
    const float* Wo = (const float*)d_in[8];
    const float* bo = (const float*)d_in[9];
    const float* lng = (const float*)d_in[10];
    const float* lnb = (const float*)d_in[11];
    float* out = (float*)d_out;

    float *gauxp, *gwq, *gwo, *gwkv, *gbkv;
    float *gao, *gaop, *gx, *gml;
    __half *gq, *gk, *gv;
    cudaGetSymbolAddress((void**)&gauxp, g_auxp);
    cudaGetSymbolAddress((void**)&gwq,   g_wq);
    cudaGetSymbolAddress((void**)&gwo,   g_wo);
    cudaGetSymbolAddress((void**)&gwkv,  g_wkv);
    cudaGetSymbolAddress((void**)&gbkv,  g_bkv);
    cudaGetSymbolAddress((void**)&gq,    g_q);
    cudaGetSymbolAddress((void**)&gk,    g_k);
    cudaGetSymbolAddress((void**)&gv,    g_v);
    cudaGetSymbolAddress((void**)&gao,   g_ao);
    cudaGetSymbolAddress((void**)&gaop,  g_aop);
    cudaGetSymbolAddress((void**)&gx,    g_x);
    cudaGetSymbolAddress((void**)&gml,   g_ml);

    const size_t AUXOUT = (size_t)2048 * 512;
    const size_t ATTN_N = (size_t)64 * 256 * 4096;
    float* attn;
    if ((size_t)out_size >= AUXOUT + ATTN_N) attn = out + AUXOUT;
    else cudaGetSymbolAddress((void**)&attn, g_attn_fb);

    static cudaStream_t sQ = nullptr, sV = nullptr;
    static cudaEvent_t evPrep = nullptr, evQ = nullptr, evK = nullptr, evV = nullptr;
    if (!sQ) {
        cudaStreamCreateWithFlags(&sQ, cudaStreamNonBlocking);
        cudaStreamCreateWithFlags(&sV, cudaStreamNonBlocking);
        cudaEventCreateWithFlags(&evPrep, cudaEventDisableTiming);
        cudaEventCreateWithFlags(&evQ,    cudaEventDisableTiming);
        cudaEventCreateWithFlags(&evK,    cudaEventDisableTiming);
        cudaEventCreateWithFlags(&evV,    cudaEventDisableTiming);
        cudaFuncSetAttribute((const void*)gemm128ca<0>, cudaFuncAttributeMaxDynamicSharedMemorySize, SMEM_PROJ_N);
        cudaFuncSetAttribute((const void*)gemm128ca<2>, cudaFuncAttributeMaxDynamicSharedMemorySize, SMEM_PROJ_N);
        cudaFuncSetAttribute((const void*)gemm_kv,      cudaFuncAttributeMaxDynamicSharedMemorySize, SMEM_PROJ_H);
        cudaFuncSetAttribute((const void*)flash_pass1,  cudaFuncAttributeMaxDynamicSharedMemorySize, SMEM_P1);
        cudaFuncSetAttribute((const void*)flash_pass2,  cudaFuncAttributeMaxDynamicSharedMemorySize, SMEM_P2);
    }

    // prep small buffers
    prep_small<<<1025, 512>>>((const float4*)aux, (const float4*)Wq, (const float4*)Wo,
                              (const float4*)Wk, (const float4*)Wv,
                              (const float4*)bk, (const float4*)bv,
                              (float4*)gauxp, (float4*)gwq, (float4*)gwo,
                              (float4*)gwkv, (float4*)gbkv);
    cudaEventRecord(evPrep, 0);

    // Q projection on side stream (half output, 0.125 folded)
    cudaStreamWaitEvent(sQ, evPrep, 0);
    gemm128ca<2><<<dim3(4, 16), 128, SMEM_PROJ_N, sQ>>>(gauxp, gwq, bq, nullptr, (float*)gq);
    cudaEventRecord(evQ, sQ);

    // K projection (half output) on main stream
    gemm_kv<<<dim3(4, 256), 128, SMEM_PROJ_H>>>(hidden, gwkv, gbkv, gk, gv, 0);
    cudaEventRecord(evK, 0);

    // V projection on side stream (concurrent with pass1)
    cudaStreamWaitEvent(sV, evK, 0);
    gemm_kv<<<dim3(4, 256), 128, SMEM_PROJ_H, sV>>>(hidden, gwkv, gbkv, gk, gv, 512);
    cudaEventRecord(evV, sV);

    // pass1 on main (needs Q + K)
    cudaStreamWaitEvent(0, evQ, 0);
    flash_pass1<<<dim3(4, 64, NSPL), 128, SMEM_P1>>>(gq, gk, gml);

    // pass2 needs V as well
    cudaStreamWaitEvent(0, evV, 0);
    flash_pass2<<<dim3(4, 64, NSPL), 128, SMEM_P2>>>(gq, gk, gv, gml, attn, gaop);
    add_ao<<<512, 512>>>((const float4*)gaop, (float4*)gao);
    // out-proj + residual
    gemm128ca<0><<<dim3(4, 16), 128, SMEM_PROJ_N>>>(gao, gwo, bo, aux, gx);
    // LayerNorm
    ln_kernel<<<2048, 256>>>(gx, lng, lnb, out);
}